// round 1
// baseline (speedup 1.0000x reference)
#include <cuda_runtime.h>
#include <math.h>

#define HDIM 1024
#define GDIM 4096   // 4*HDIM
#define TT 28
#define DD 28
#define BB 4096
#define KBATCH 8

#define BM 128
#define BN 32
#define BK 8

// Persistent scratch (no allocations allowed in kernel_launch)
__device__ float g_h[2][(size_t)BB * HDIM];   // ping-pong hidden state
__device__ float g_c[(size_t)BB * HDIM];      // cell state (in-place)
__device__ float g_hk[2][KBATCH * HDIM];      // key-pass hidden
__device__ float g_ck[KBATCH * HDIM];         // key-pass cell
__device__ float g_h0[HDIM];
__device__ float g_c0[HDIM];

__device__ __forceinline__ float sigmoidf_(float x) {
    return 1.0f / (1.0f + __expf(-x));
}

// ---------------------------------------------------------------------------
// Data-pass LSTM step: fused GEMM [BB x (HDIM+DD)] @ [(HDIM+DD) x 4*HDIM]
// + LSTM cell update. Gates packed as float4 {i,f,g,o} per (m,n).
// ---------------------------------------------------------------------------
__global__ __launch_bounds__(256, 2)
void data_step(const float* __restrict__ x,
               const float* __restrict__ Wih,
               const float* __restrict__ Whh,
               const float* __restrict__ bias,
               int t, int p)
{
    __shared__ float  As[BK][BM];
    __shared__ float4 Bs[BK][BN];

    const float* __restrict__ h_in  = g_h[p];
    float*       __restrict__ h_out = g_h[1 - p];

    const int tid = threadIdx.x;
    const int m0 = blockIdx.y * BM;
    const int n0 = blockIdx.x * BN;
    const int tx = tid & 15;   // n-pair index (0..15) -> cols tx*2, tx*2+1
    const int ty = tid >> 4;   // m-group (0..15)     -> rows ty*8 .. ty*8+7

    float4 acc[8][2];
#pragma unroll
    for (int r = 0; r < 8; r++)
#pragma unroll
        for (int c = 0; c < 2; c++)
            acc[r][c] = make_float4(0.f, 0.f, 0.f, 0.f);

    const int lm = tid >> 1;          // A-load row 0..127
    const int lk = (tid & 1) * 4;     // A-load k offset {0,4}
    const int wk = tid >> 5;          // B-load k row 0..7
    const int wj = tid & 31;          // B-load col 0..31

#define INNER_TILE()                                                        \
    _Pragma("unroll")                                                       \
    for (int k = 0; k < BK; k++) {                                          \
        float4 a0 = *(const float4*)&As[k][ty * 8];                         \
        float4 a1 = *(const float4*)&As[k][ty * 8 + 4];                     \
        float4 b0 = Bs[k][tx * 2];                                          \
        float4 b1 = Bs[k][tx * 2 + 1];                                      \
        float am[8] = {a0.x, a0.y, a0.z, a0.w, a1.x, a1.y, a1.z, a1.w};     \
        _Pragma("unroll")                                                   \
        for (int r = 0; r < 8; r++) {                                       \
            acc[r][0].x += am[r] * b0.x; acc[r][0].y += am[r] * b0.y;       \
            acc[r][0].z += am[r] * b0.z; acc[r][0].w += am[r] * b0.w;       \
            acc[r][1].x += am[r] * b1.x; acc[r][1].y += am[r] * b1.y;       \
            acc[r][1].z += am[r] * b1.z; acc[r][1].w += am[r] * b1.w;       \
        }                                                                   \
    }

    // ---- main K loop over h (K = HDIM) ----
    for (int k0 = 0; k0 < HDIM; k0 += BK) {
        float4 av = *(const float4*)(h_in + (size_t)(m0 + lm) * HDIM + k0 + lk);
        As[lk + 0][lm] = av.x; As[lk + 1][lm] = av.y;
        As[lk + 2][lm] = av.z; As[lk + 3][lm] = av.w;
        const float* wr = Whh + (size_t)(k0 + wk) * GDIM + n0 + wj;
        Bs[wk][wj] = make_float4(wr[0], wr[HDIM], wr[2 * HDIM], wr[3 * HDIM]);
        __syncthreads();
        INNER_TILE();
        __syncthreads();
    }

    // ---- tail over x_t (K = DD = 28, padded to 32) ----
    for (int k0 = 0; k0 < 32; k0 += BK) {
#pragma unroll
        for (int i = 0; i < 4; i++) {
            int k = k0 + lk + i;
            As[lk + i][lm] = (k < DD)
                ? x[(size_t)(m0 + lm) * (TT * DD) + t * DD + k] : 0.0f;
        }
        if (k0 + wk < DD) {
            const float* wr = Wih + (size_t)(k0 + wk) * GDIM + n0 + wj;
            Bs[wk][wj] = make_float4(wr[0], wr[HDIM], wr[2 * HDIM], wr[3 * HDIM]);
        } else {
            Bs[wk][wj] = make_float4(0.f, 0.f, 0.f, 0.f);
        }
        __syncthreads();
        INNER_TILE();
        __syncthreads();
    }

    // ---- fused LSTM cell epilogue ----
#pragma unroll
    for (int r = 0; r < 8; r++) {
        int m = m0 + ty * 8 + r;
#pragma unroll
        for (int c = 0; c < 2; c++) {
            int n = n0 + tx * 2 + c;
            float4 g = acc[r][c];
            float gi = g.x + bias[n];
            float gf = g.y + bias[HDIM + n];
            float gg = g.z + bias[2 * HDIM + n];
            float go = g.w + bias[3 * HDIM + n];
            size_t idx = (size_t)m * HDIM + n;
            float cv = g_c[idx];
            float cn = sigmoidf_(gf) * cv + sigmoidf_(gi) * tanhf(gg);
            g_c[idx] = cn;
            h_out[idx] = sigmoidf_(go) * tanhf(cn);
        }
    }
#undef INNER_TILE
}

// ---------------------------------------------------------------------------
// Key-pass LSTM step: batch = 8 (thin GEMM). 32 blocks, 256 threads:
// each thread owns one (m, n) with 4 gates.
// ---------------------------------------------------------------------------
#define KBK 16
__global__ __launch_bounds__(256, 4)
void key_step(const float* __restrict__ key,
              const float* __restrict__ Wih,
              const float* __restrict__ Whh,
              const float* __restrict__ bias,
              int t, int p)
{
    __shared__ float  As[KBK][KBATCH];
    __shared__ float4 Bs[KBK][BN];

    const float* __restrict__ h_in  = g_hk[p];
    float*       __restrict__ h_out = g_hk[1 - p];

    const int tid = threadIdx.x;
    const int n0 = blockIdx.x * BN;
    const int n = tid & 31;
    const int m = tid >> 5;   // 0..7
    float4 acc = make_float4(0.f, 0.f, 0.f, 0.f);

    for (int k0 = 0; k0 < HDIM; k0 += KBK) {
        if (tid < KBK * KBATCH) {
            int km = tid & 7, kk = tid >> 3;
            As[kk][km] = h_in[km * HDIM + k0 + kk];
        }
        {
            int bk = tid >> 5;
            const float* w0 = Whh + (size_t)(k0 + bk) * GDIM + n0 + n;
            Bs[bk][n] = make_float4(w0[0], w0[HDIM], w0[2 * HDIM], w0[3 * HDIM]);
            const float* w1 = Whh + (size_t)(k0 + bk + 8) * GDIM + n0 + n;
            Bs[bk + 8][n] = make_float4(w1[0], w1[HDIM], w1[2 * HDIM], w1[3 * HDIM]);
        }
        __syncthreads();
#pragma unroll
        for (int k = 0; k < KBK; k++) {
            float a = As[k][m];
            float4 b = Bs[k][n];
            acc.x += a * b.x; acc.y += a * b.y;
            acc.z += a * b.z; acc.w += a * b.w;
        }
        __syncthreads();
    }

    // x tail K = 28 (padded to 32)
    for (int k0 = 0; k0 < 32; k0 += KBK) {
        if (tid < KBK * KBATCH) {
            int km = tid & 7, kk = tid >> 3;
            int k = k0 + kk;
            As[kk][km] = (k < DD) ? key[km * (TT * DD) + t * DD + k] : 0.0f;
        }
        {
            int bk = tid >> 5;
            int k1 = k0 + bk, k2 = k0 + bk + 8;
            if (k1 < DD) {
                const float* w = Wih + (size_t)k1 * GDIM + n0 + n;
                Bs[bk][n] = make_float4(w[0], w[HDIM], w[2 * HDIM], w[3 * HDIM]);
            } else Bs[bk][n] = make_float4(0.f, 0.f, 0.f, 0.f);
            if (k2 < DD) {
                const float* w = Wih + (size_t)k2 * GDIM + n0 + n;
                Bs[bk + 8][n] = make_float4(w[0], w[HDIM], w[2 * HDIM], w[3 * HDIM]);
            } else Bs[bk + 8][n] = make_float4(0.f, 0.f, 0.f, 0.f);
        }
        __syncthreads();
#pragma unroll
        for (int k = 0; k < KBK; k++) {
            float a = As[k][m];
            float4 b = Bs[k][n];
            acc.x += a * b.x; acc.y += a * b.y;
            acc.z += a * b.z; acc.w += a * b.w;
        }
        __syncthreads();
    }

    int nn = n0 + n;
    float gi = acc.x + bias[nn];
    float gf = acc.y + bias[HDIM + nn];
    float gg = acc.z + bias[2 * HDIM + nn];
    float go = acc.w + bias[3 * HDIM + nn];
    int idx = m * HDIM + nn;
    float cv = g_ck[idx];
    float cn = sigmoidf_(gf) * cv + sigmoidf_(gi) * tanhf(gg);
    g_ck[idx] = cn;
    h_out[idx] = sigmoidf_(go) * tanhf(cn);
}

// ---------------------------------------------------------------------------
__global__ void key_init()
{
    int i = blockIdx.x * blockDim.x + threadIdx.x;
    if (i < KBATCH * HDIM) { g_hk[0][i] = 0.f; g_ck[i] = 0.f; }
}

__global__ void key_mean(int p)
{
    int n = blockIdx.x * blockDim.x + threadIdx.x;
    if (n < HDIM) {
        float sh = 0.f, sc = 0.f;
        for (int m = 0; m < KBATCH; m++) {
            sh += g_hk[p][m * HDIM + n];
            sc += g_ck[m * HDIM + n];
        }
        g_h0[n] = sh * (1.0f / KBATCH);
        g_c0[n] = sc * (1.0f / KBATCH);
    }
}

__global__ void bcast_init()
{
    size_t total = (size_t)BB * HDIM;
    for (size_t i = (size_t)blockIdx.x * blockDim.x + threadIdx.x;
         i < total; i += (size_t)gridDim.x * blockDim.x) {
        int n = (int)(i & (HDIM - 1));
        g_h[0][i] = g_h0[n];
        g_c[i]    = g_c0[n];
    }
}

// ---------------------------------------------------------------------------
// Classifier: out[B,10] = h @ W_cls + b_cls. One warp per row.
// ---------------------------------------------------------------------------
__global__ void classify(const float* __restrict__ Wcls,
                         const float* __restrict__ bcls,
                         float* __restrict__ out, int p)
{
    int gwarp = (blockIdx.x * blockDim.x + threadIdx.x) >> 5;
    int lane = threadIdx.x & 31;
    if (gwarp >= BB) return;
    const float* hr = g_h[p] + (size_t)gwarp * HDIM;
    float acc[10];
#pragma unroll
    for (int c = 0; c < 10; c++) acc[c] = 0.f;
    for (int k = lane; k < HDIM; k += 32) {
        float hv = hr[k];
#pragma unroll
        for (int c = 0; c < 10; c++) acc[c] += hv * Wcls[k * 10 + c];
    }
#pragma unroll
    for (int c = 0; c < 10; c++) {
#pragma unroll
        for (int off = 16; off > 0; off >>= 1)
            acc[c] += __shfl_down_sync(0xffffffffu, acc[c], off);
    }
    if (lane == 0) {
#pragma unroll
        for (int c = 0; c < 10; c++)
            out[(size_t)gwarp * 10 + c] = acc[c] + bcls[c];
    }
}

// ---------------------------------------------------------------------------
extern "C" void kernel_launch(void* const* d_in, const int* in_sizes, int n_in,
                              void* d_out, int out_size)
{
    const float* x    = (const float*)d_in[0];
    const float* key  = (const float*)d_in[1];
    const float* Wih  = (const float*)d_in[2];
    const float* Whh  = (const float*)d_in[3];
    const float* b    = (const float*)d_in[4];
    const float* Wcls = (const float*)d_in[5];
    const float* bcls = (const float*)d_in[6];
    float* out = (float*)d_out;

    // Key pass (batch 8), zero init
    key_init<<<(KBATCH * HDIM + 255) / 256, 256>>>();
    for (int t = 0; t < TT; t++)
        key_step<<<HDIM / BN, 256>>>(key, Wih, Whh, b, t, t & 1);
    // After 28 steps (even), final key state sits in g_hk[0]
    key_mean<<<(HDIM + 255) / 256, 256>>>(0);
    bcast_init<<<1024, 256>>>();

    // Data pass (batch 4096)
    dim3 grid(HDIM / BN, BB / BM);
    for (int t = 0; t < TT; t++)
        data_step<<<grid, 256>>>(x, Wih, Whh, b, t, t & 1);
    // After 28 steps, final h sits in g_h[0]
    classify<<<BB / 8, 256>>>(Wcls, bcls, out, 0);
}

// round 2
// speedup vs baseline: 1.0005x; 1.0005x over previous
#include <cuda_runtime.h>
#include <math.h>

#define HDIM 1024
#define GDIM 4096   // 4*HDIM
#define TT 28
#define DD 28
#define BB 4096
#define KBATCH 8

#define BM 128
#define BN 32
#define BK 8

// Persistent scratch (no allocations allowed in kernel_launch)
__device__ float g_h[2][(size_t)BB * HDIM];   // ping-pong hidden state
__device__ float g_c[(size_t)BB * HDIM];      // cell state (in-place)
__device__ float g_hk[2][KBATCH * HDIM];      // key-pass hidden
__device__ float g_ck[KBATCH * HDIM];         // key-pass cell
__device__ float g_h0[HDIM];
__device__ float g_c0[HDIM];

__device__ __forceinline__ float sigmoidf_(float x) {
    return 1.0f / (1.0f + __expf(-x));
}

// ---------------------------------------------------------------------------
// Data-pass LSTM step: fused GEMM [BB x (HDIM+DD)] @ [(HDIM+DD) x 4*HDIM]
// + LSTM cell update. Gates packed as float4 {i,f,g,o} per (m,n).
// ---------------------------------------------------------------------------
__global__ __launch_bounds__(256, 2)
void data_step(const float* __restrict__ x,
               const float* __restrict__ Wih,
               const float* __restrict__ Whh,
               const float* __restrict__ bias,
               int t, int p)
{
    __shared__ float  As[BK][BM];
    __shared__ float4 Bs[BK][BN];

    const float* __restrict__ h_in  = g_h[p];
    float*       __restrict__ h_out = g_h[1 - p];

    const int tid = threadIdx.x;
    const int m0 = blockIdx.y * BM;
    const int n0 = blockIdx.x * BN;
    const int tx = tid & 15;   // n-pair index (0..15) -> cols tx*2, tx*2+1
    const int ty = tid >> 4;   // m-group (0..15)     -> rows ty*8 .. ty*8+7

    float4 acc[8][2];
#pragma unroll
    for (int r = 0; r < 8; r++)
#pragma unroll
        for (int c = 0; c < 2; c++)
            acc[r][c] = make_float4(0.f, 0.f, 0.f, 0.f);

    const int lm = tid >> 1;          // A-load row 0..127
    const int lk = (tid & 1) * 4;     // A-load k offset {0,4}
    const int wk = tid >> 5;          // B-load k row 0..7
    const int wj = tid & 31;          // B-load col 0..31

#define INNER_TILE()                                                        \
    _Pragma("unroll")                                                       \
    for (int k = 0; k < BK; k++) {                                          \
        float4 a0 = *(const float4*)&As[k][ty * 8];                         \
        float4 a1 = *(const float4*)&As[k][ty * 8 + 4];                     \
        float4 b0 = Bs[k][tx * 2];                                          \
        float4 b1 = Bs[k][tx * 2 + 1];                                      \
        float am[8] = {a0.x, a0.y, a0.z, a0.w, a1.x, a1.y, a1.z, a1.w};     \
        _Pragma("unroll")                                                   \
        for (int r = 0; r < 8; r++) {                                       \
            acc[r][0].x += am[r] * b0.x; acc[r][0].y += am[r] * b0.y;       \
            acc[r][0].z += am[r] * b0.z; acc[r][0].w += am[r] * b0.w;       \
            acc[r][1].x += am[r] * b1.x; acc[r][1].y += am[r] * b1.y;       \
            acc[r][1].z += am[r] * b1.z; acc[r][1].w += am[r] * b1.w;       \
        }                                                                   \
    }

    // ---- main K loop over h (K = HDIM) ----
    for (int k0 = 0; k0 < HDIM; k0 += BK) {
        float4 av = *(const float4*)(h_in + (size_t)(m0 + lm) * HDIM + k0 + lk);
        As[lk + 0][lm] = av.x; As[lk + 1][lm] = av.y;
        As[lk + 2][lm] = av.z; As[lk + 3][lm] = av.w;
        const float* wr = Whh + (size_t)(k0 + wk) * GDIM + n0 + wj;
        Bs[wk][wj] = make_float4(wr[0], wr[HDIM], wr[2 * HDIM], wr[3 * HDIM]);
        __syncthreads();
        INNER_TILE();
        __syncthreads();
    }

    // ---- tail over x_t (K = DD = 28, padded to 32) ----
    for (int k0 = 0; k0 < 32; k0 += BK) {
#pragma unroll
        for (int i = 0; i < 4; i++) {
            int k = k0 + lk + i;
            As[lk + i][lm] = (k < DD)
                ? x[(size_t)(m0 + lm) * (TT * DD) + t * DD + k] : 0.0f;
        }
        if (k0 + wk < DD) {
            const float* wr = Wih + (size_t)(k0 + wk) * GDIM + n0 + wj;
            Bs[wk][wj] = make_float4(wr[0], wr[HDIM], wr[2 * HDIM], wr[3 * HDIM]);
        } else {
            Bs[wk][wj] = make_float4(0.f, 0.f, 0.f, 0.f);
        }
        __syncthreads();
        INNER_TILE();
        __syncthreads();
    }

    // ---- fused LSTM cell epilogue ----
#pragma unroll
    for (int r = 0; r < 8; r++) {
        int m = m0 + ty * 8 + r;
#pragma unroll
        for (int c = 0; c < 2; c++) {
            int n = n0 + tx * 2 + c;
            float4 g = acc[r][c];
            float gi = g.x + bias[n];
            float gf = g.y + bias[HDIM + n];
            float gg = g.z + bias[2 * HDIM + n];
            float go = g.w + bias[3 * HDIM + n];
            size_t idx = (size_t)m * HDIM + n;
            float cv = g_c[idx];
            float cn = sigmoidf_(gf) * cv + sigmoidf_(gi) * tanhf(gg);
            g_c[idx] = cn;
            h_out[idx] = sigmoidf_(go) * tanhf(cn);
        }
    }
#undef INNER_TILE
}

// ---------------------------------------------------------------------------
// Key-pass LSTM step: batch = 8 (thin GEMM). 32 blocks, 256 threads:
// each thread owns one (m, n) with 4 gates.
// ---------------------------------------------------------------------------
#define KBK 16
__global__ __launch_bounds__(256, 4)
void key_step(const float* __restrict__ key,
              const float* __restrict__ Wih,
              const float* __restrict__ Whh,
              const float* __restrict__ bias,
              int t, int p)
{
    __shared__ float  As[KBK][KBATCH];
    __shared__ float4 Bs[KBK][BN];

    const float* __restrict__ h_in  = g_hk[p];
    float*       __restrict__ h_out = g_hk[1 - p];

    const int tid = threadIdx.x;
    const int n0 = blockIdx.x * BN;
    const int n = tid & 31;
    const int m = tid >> 5;   // 0..7
    float4 acc = make_float4(0.f, 0.f, 0.f, 0.f);

    for (int k0 = 0; k0 < HDIM; k0 += KBK) {
        if (tid < KBK * KBATCH) {
            int km = tid & 7, kk = tid >> 3;
            As[kk][km] = h_in[km * HDIM + k0 + kk];
        }
        {
            int bk = tid >> 5;
            const float* w0 = Whh + (size_t)(k0 + bk) * GDIM + n0 + n;
            Bs[bk][n] = make_float4(w0[0], w0[HDIM], w0[2 * HDIM], w0[3 * HDIM]);
            const float* w1 = Whh + (size_t)(k0 + bk + 8) * GDIM + n0 + n;
            Bs[bk + 8][n] = make_float4(w1[0], w1[HDIM], w1[2 * HDIM], w1[3 * HDIM]);
        }
        __syncthreads();
#pragma unroll
        for (int k = 0; k < KBK; k++) {
            float a = As[k][m];
            float4 b = Bs[k][n];
            acc.x += a * b.x; acc.y += a * b.y;
            acc.z += a * b.z; acc.w += a * b.w;
        }
        __syncthreads();
    }

    // x tail K = 28 (padded to 32)
    for (int k0 = 0; k0 < 32; k0 += KBK) {
        if (tid < KBK * KBATCH) {
            int km = tid & 7, kk = tid >> 3;
            int k = k0 + kk;
            As[kk][km] = (k < DD) ? key[km * (TT * DD) + t * DD + k] : 0.0f;
        }
        {
            int bk = tid >> 5;
            int k1 = k0 + bk, k2 = k0 + bk + 8;
            if (k1 < DD) {
                const float* w = Wih + (size_t)k1 * GDIM + n0 + n;
                Bs[bk][n] = make_float4(w[0], w[HDIM], w[2 * HDIM], w[3 * HDIM]);
            } else Bs[bk][n] = make_float4(0.f, 0.f, 0.f, 0.f);
            if (k2 < DD) {
                const float* w = Wih + (size_t)k2 * GDIM + n0 + n;
                Bs[bk + 8][n] = make_float4(w[0], w[HDIM], w[2 * HDIM], w[3 * HDIM]);
            } else Bs[bk + 8][n] = make_float4(0.f, 0.f, 0.f, 0.f);
        }
        __syncthreads();
#pragma unroll
        for (int k = 0; k < KBK; k++) {
            float a = As[k][m];
            float4 b = Bs[k][n];
            acc.x += a * b.x; acc.y += a * b.y;
            acc.z += a * b.z; acc.w += a * b.w;
        }
        __syncthreads();
    }

    int nn = n0 + n;
    float gi = acc.x + bias[nn];
    float gf = acc.y + bias[HDIM + nn];
    float gg = acc.z + bias[2 * HDIM + nn];
    float go = acc.w + bias[3 * HDIM + nn];
    int idx = m * HDIM + nn;
    float cv = g_ck[idx];
    float cn = sigmoidf_(gf) * cv + sigmoidf_(gi) * tanhf(gg);
    g_ck[idx] = cn;
    h_out[idx] = sigmoidf_(go) * tanhf(cn);
}

// ---------------------------------------------------------------------------
__global__ void key_init()
{
    int i = blockIdx.x * blockDim.x + threadIdx.x;
    if (i < KBATCH * HDIM) { g_hk[0][i] = 0.f; g_ck[i] = 0.f; }
}

__global__ void key_mean(int p)
{
    int n = blockIdx.x * blockDim.x + threadIdx.x;
    if (n < HDIM) {
        float sh = 0.f, sc = 0.f;
        for (int m = 0; m < KBATCH; m++) {
            sh += g_hk[p][m * HDIM + n];
            sc += g_ck[m * HDIM + n];
        }
        g_h0[n] = sh * (1.0f / KBATCH);
        g_c0[n] = sc * (1.0f / KBATCH);
    }
}

__global__ void bcast_init()
{
    size_t total = (size_t)BB * HDIM;
    for (size_t i = (size_t)blockIdx.x * blockDim.x + threadIdx.x;
         i < total; i += (size_t)gridDim.x * blockDim.x) {
        int n = (int)(i & (HDIM - 1));
        g_h[0][i] = g_h0[n];
        g_c[i]    = g_c0[n];
    }
}

// ---------------------------------------------------------------------------
// Classifier: out[B,10] = h @ W_cls + b_cls. One warp per row.
// ---------------------------------------------------------------------------
__global__ void classify(const float* __restrict__ Wcls,
                         const float* __restrict__ bcls,
                         float* __restrict__ out, int p)
{
    int gwarp = (blockIdx.x * blockDim.x + threadIdx.x) >> 5;
    int lane = threadIdx.x & 31;
    if (gwarp >= BB) return;
    const float* hr = g_h[p] + (size_t)gwarp * HDIM;
    float acc[10];
#pragma unroll
    for (int c = 0; c < 10; c++) acc[c] = 0.f;
    for (int k = lane; k < HDIM; k += 32) {
        float hv = hr[k];
#pragma unroll
        for (int c = 0; c < 10; c++) acc[c] += hv * Wcls[k * 10 + c];
    }
#pragma unroll
    for (int c = 0; c < 10; c++) {
#pragma unroll
        for (int off = 16; off > 0; off >>= 1)
            acc[c] += __shfl_down_sync(0xffffffffu, acc[c], off);
    }
    if (lane == 0) {
#pragma unroll
        for (int c = 0; c < 10; c++)
            out[(size_t)gwarp * 10 + c] = acc[c] + bcls[c];
    }
}

// ---------------------------------------------------------------------------
extern "C" void kernel_launch(void* const* d_in, const int* in_sizes, int n_in,
                              void* d_out, int out_size)
{
    const float* x    = (const float*)d_in[0];
    const float* key  = (const float*)d_in[1];
    const float* Wih  = (const float*)d_in[2];
    const float* Whh  = (const float*)d_in[3];
    const float* b    = (const float*)d_in[4];
    const float* Wcls = (const float*)d_in[5];
    const float* bcls = (const float*)d_in[6];
    float* out = (float*)d_out;

    // Key pass (batch 8), zero init
    key_init<<<(KBATCH * HDIM + 255) / 256, 256>>>();
    for (int t = 0; t < TT; t++)
        key_step<<<HDIM / BN, 256>>>(key, Wih, Whh, b, t, t & 1);
    // After 28 steps (even), final key state sits in g_hk[0]
    key_mean<<<(HDIM + 255) / 256, 256>>>(0);
    bcast_init<<<1024, 256>>>();

    // Data pass (batch 4096)
    dim3 grid(HDIM / BN, BB / BM);
    for (int t = 0; t < TT; t++)
        data_step<<<grid, 256>>>(x, Wih, Whh, b, t, t & 1);
    // After 28 steps, final h sits in g_h[0]
    classify<<<BB / 8, 256>>>(Wcls, bcls, out, 0);
}

// round 6
// speedup vs baseline: 2.9669x; 2.9654x over previous
#include <cuda_runtime.h>
#include <cuda_bf16.h>
#include <cstdint>
#include <math.h>

#define HDIM 1024
#define GDIM 4096
#define TT 28
#define DD 28
#define BB 4096
#define KBATCH 8

// GEMM geometry (per data step): C[4096 x 4096gates] = A[4096 x K'] B[K' x 4096]
// K' = 3 terms x 17 chunks x 64 = 3264 (terms: AhiBhi, AhiBlo, AloBhi)
#define KC 64
#define CPT 17            // chunks per term (16 h-chunks + 1 x-chunk)
#define CHUNKS 51         // 3*CPT
#define NSTAGE 3
#define TILE_BYTES 16384  // 128 x 64 bf16
#define STAGE_BYTES 32768 // A tile + B tile
#define SMEM_DATA (NSTAGE * STAGE_BYTES)
#define MBK 32            // 4096/128 M-blocks
#define NBK 32            // 1024/32 out-blocks (128 gate-cols per CTA)

// ---------------- persistent scratch ----------------
__device__ __nv_bfloat16 g_Wh[NBK][CPT][8192];
__device__ __nv_bfloat16 g_Wl[NBK][CPT][8192];
__device__ __nv_bfloat16 g_Ah[2][MBK][16][8192];   // h tiles, ping-pong
__device__ __nv_bfloat16 g_Al[2][MBK][16][8192];
__device__ __nv_bfloat16 g_xh[TT][MBK][8192];
__device__ __nv_bfloat16 g_xl[TT][MBK][8192];
__device__ float g_c[(size_t)BB * HDIM];
__device__ float g_hf[(size_t)BB * HDIM];
__device__ float g_hk[2][KBATCH * HDIM];
__device__ float g_ck[KBATCH * HDIM];
__device__ float g_gk[KBATCH][GDIM];
__device__ float g_h0[HDIM];
__device__ float g_c0[HDIM];

// ---------------- helpers ----------------
__device__ __forceinline__ float sigmoidf_(float x) { return 1.0f / (1.0f + __expf(-x)); }

// swizzled byte offset within a 128x64 bf16 tile (128B rows, SW128 16B groups)
__device__ __forceinline__ uint32_t aoff(int row, int kk) {
    return (uint32_t)(row * 128 + ((((kk >> 3) ^ row) & 7) << 4) + (kk & 7) * 2);
}

__device__ __forceinline__ uint32_t smem_u32(const void* p) {
    uint32_t a;
    asm("{ .reg .u64 t; cvta.to.shared.u64 t, %1; cvt.u32.u64 %0, t; }" : "=r"(a) : "l"(p));
    return a;
}

__device__ __forceinline__ uint32_t bpack(float v0, float v1) {
    __nv_bfloat162 p = __floats2bfloat162_rn(v0, v1);
    return *(uint32_t*)&p;
}

#define CP_ASYNC16(dst, src) \
    asm volatile("cp.async.cg.shared.global [%0], [%1], 16;" :: "r"(dst), "l"(src))
#define CP_COMMIT() asm volatile("cp.async.commit_group;" ::: "memory")
#define CP_WAIT2()  asm volatile("cp.async.wait_group 2;" ::: "memory")

#define LDMX4(r0, r1, r2, r3, addr) \
    asm volatile("ldmatrix.sync.aligned.m8n8.x4.shared.b16 {%0,%1,%2,%3}, [%4];" \
        : "=r"(r0), "=r"(r1), "=r"(r2), "=r"(r3) : "r"(addr))
#define LDMX2(r0, r1, addr) \
    asm volatile("ldmatrix.sync.aligned.m8n8.x2.shared.b16 {%0,%1}, [%2];" \
        : "=r"(r0), "=r"(r1) : "r"(addr))
#define MMA16816(d, a, b0, b1) \
    asm volatile("mma.sync.aligned.m16n8k16.row.col.f32.bf16.bf16.f32 " \
        "{%0,%1,%2,%3},{%4,%5,%6,%7},{%8,%9},{%0,%1,%2,%3};" \
        : "+f"((d)[0]), "+f"((d)[1]), "+f"((d)[2]), "+f"((d)[3]) \
        : "r"((a)[0]), "r"((a)[1]), "r"((a)[2]), "r"((a)[3]), "r"(b0), "r"(b1))

// ---------------------------------------------------------------------------
// prep: bf16 hi/lo split of weights into swizzled [n][k] tiles.
// B tile col layout (128): warp w (n>>5), gate ((n>>3)&3), out_local (n&7)
// -> W column = gate*1024 + nb*32 + w*8 + ol
// ---------------------------------------------------------------------------
__global__ void prep_W(const float* __restrict__ Wih, const float* __restrict__ Whh)
{
    int kc = blockIdx.x, nb = blockIdx.y;
    int n = threadIdx.x & 127, kh = threadIdx.x >> 7;
    int w = n >> 5, gate = (n >> 3) & 3, ol = n & 7;
    int col = gate * HDIM + nb * 32 + w * 8 + ol;
    char* th = (char*)&g_Wh[nb][kc][0];
    char* tl = (char*)&g_Wl[nb][kc][0];
#pragma unroll
    for (int kk = kh * 32; kk < kh * 32 + 32; kk += 2) {
        float v0, v1;
        if (kc < 16) {
            size_t kg = (size_t)(kc * 64 + kk);
            v0 = Whh[kg * GDIM + col];
            v1 = Whh[(kg + 1) * GDIM + col];
        } else {
            v0 = (kk < DD) ? Wih[(size_t)kk * GDIM + col] : 0.f;
            v1 = (kk + 1 < DD) ? Wih[(size_t)(kk + 1) * GDIM + col] : 0.f;
        }
        float h0 = __bfloat162float(__float2bfloat16(v0));
        float h1 = __bfloat162float(__float2bfloat16(v1));
        uint32_t off = aoff(n, kk);
        *(uint32_t*)(th + off) = bpack(h0, h1);
        *(uint32_t*)(tl + off) = bpack(v0 - h0, v1 - h1);
    }
}

__global__ void prep_x(const float* __restrict__ x)
{
    int mb = blockIdx.x, t = blockIdx.y;
    int r = threadIdx.x;
    int m = mb * 128 + r;
    char* th = (char*)&g_xh[t][mb][0];
    char* tl = (char*)&g_xl[t][mb][0];
#pragma unroll
    for (int kk = 0; kk < KC; kk += 2) {
        float v0 = (kk < DD) ? x[((size_t)m * TT + t) * DD + kk] : 0.f;
        float v1 = (kk + 1 < DD) ? x[((size_t)m * TT + t) * DD + kk + 1] : 0.f;
        float h0 = __bfloat162float(__float2bfloat16(v0));
        float h1 = __bfloat162float(__float2bfloat16(v1));
        uint32_t off = aoff(r, kk);
        *(uint32_t*)(th + off) = bpack(h0, h1);
        *(uint32_t*)(tl + off) = bpack(v0 - h0, v1 - h1);
    }
}

// ---------------------------------------------------------------------------
// Data step: bf16 mma.sync GEMM (3-term K-folded) + fused LSTM cell
// ---------------------------------------------------------------------------
__device__ __forceinline__ void load_chunk(uint32_t smb, int tid, int c,
                                           int t, int pp, int mb, int nb)
{
    if (c < CHUNKS) {
        int term = (c >= 2 * CPT) ? 2 : (c >= CPT ? 1 : 0);
        int kc = c - term * CPT;
        const char* as;
        if (kc == 16)
            as = (const char*)((term < 2) ? &g_xh[t][mb][0] : &g_xl[t][mb][0]);
        else
            as = (const char*)((term < 2) ? &g_Ah[pp][mb][kc][0] : &g_Al[pp][mb][kc][0]);
        const char* bs = (const char*)((term == 1) ? &g_Wl[nb][kc][0] : &g_Wh[nb][kc][0]);
        uint32_t dst = smb + (c % NSTAGE) * STAGE_BYTES;
        int o = tid * 16;
#pragma unroll
        for (int i = 0; i < 4; i++) {
            CP_ASYNC16(dst + o, as + o);
            CP_ASYNC16(dst + TILE_BYTES + o, bs + o);
            o += 4096;
        }
    }
    CP_COMMIT();
}

__global__ void __launch_bounds__(256, 2)
data_step(const float* __restrict__ bias, int t, int pp)
{
    extern __shared__ __align__(128) char sm[];
    const uint32_t smb = smem_u32(sm);
    const int tid = threadIdx.x, wid = tid >> 5, lane = tid & 31;
    const int nb = blockIdx.x, mb = blockIdx.y;
    const int mw = (wid >> 2) * 64;       // warp m offset
    const int nw = (wid & 3) * 32;        // warp n(col) offset

    float acc[4][4][4];
#pragma unroll
    for (int i = 0; i < 4; i++)
#pragma unroll
        for (int j = 0; j < 4; j++)
#pragma unroll
            for (int q = 0; q < 4; q++) acc[i][j][q] = 0.f;

    load_chunk(smb, tid, 0, t, pp, mb, nb);
    load_chunk(smb, tid, 1, t, pp, mb, nb);
    load_chunk(smb, tid, 2, t, pp, mb, nb);

    // precomputed lane geometry
    const int a_row7 = lane & 7;
    const int a_sel8 = ((lane >> 3) & 1) * 8;
    const int a_ghalf = lane >> 4;
    const int ln = lane & 15;
    const int b_n7 = ln & 7;
    const int b_ghalf = ln >> 3;

    for (int c = 0; c < CHUNKS; c++) {
        CP_WAIT2();
        __syncthreads();
        uint32_t sa = smb + (c % NSTAGE) * STAGE_BYTES;
        uint32_t sbB = sa + TILE_BYTES;
#pragma unroll
        for (int kb = 0; kb < 4; kb++) {
            uint32_t a[4][4];
#pragma unroll
            for (int mi = 0; mi < 4; mi++) {
                int row = mw + mi * 16 + a_sel8 + a_row7;
                int grp = 2 * kb + a_ghalf;
                uint32_t ad = sa + row * 128 + (((grp ^ row) & 7) << 4);
                LDMX4(a[mi][0], a[mi][1], a[mi][2], a[mi][3], ad);
            }
#pragma unroll
            for (int ni = 0; ni < 4; ni++) {
                int n = nw + ni * 8 + b_n7;
                int grp = 2 * kb + b_ghalf;
                uint32_t bd = sbB + n * 128 + (((grp ^ n) & 7) << 4);
                uint32_t b0, b1;
                LDMX2(b0, b1, bd);
#pragma unroll
                for (int mi = 0; mi < 4; mi++)
                    MMA16816(acc[mi][ni], a[mi], b0, b1);
            }
        }
        __syncthreads();
        load_chunk(smb, tid, c + NSTAGE, t, pp, mb, nb);
    }

    // ---- fused LSTM cell epilogue ----
    // thread owns rows mw+mi*16+(lane>>2)+{0,8}, outs o0,o0+1 with all 4 gates
    const int r4 = lane >> 2;
    const int o0 = nb * 32 + (wid & 3) * 8 + (lane & 3) * 2;
    const int chunk = nb >> 1;
    const int kk0 = o0 & 63;
    float bi0 = bias[o0],            bi1 = bias[o0 + 1];
    float bf0 = bias[HDIM + o0],     bf1 = bias[HDIM + o0 + 1];
    float bg0 = bias[2*HDIM + o0],   bg1 = bias[2*HDIM + o0 + 1];
    float bo0 = bias[3*HDIM + o0],   bo1 = bias[3*HDIM + o0 + 1];
    char* th = (char*)&g_Ah[pp ^ 1][mb][chunk][0];
    char* tl = (char*)&g_Al[pp ^ 1][mb][chunk][0];

#pragma unroll
    for (int mi = 0; mi < 4; mi++) {
#pragma unroll
        for (int b2 = 0; b2 < 2; b2++) {
            int mrow = mw + mi * 16 + r4 + b2 * 8;
            int m = mb * 128 + mrow;
            size_t cidx = (size_t)m * HDIM + o0;
            float2 cold = *(float2*)&g_c[cidx];
            float gi0 = acc[mi][0][b2 * 2],     gi1 = acc[mi][0][b2 * 2 + 1];
            float gf0 = acc[mi][1][b2 * 2],     gf1 = acc[mi][1][b2 * 2 + 1];
            float gg0 = acc[mi][2][b2 * 2],     gg1 = acc[mi][2][b2 * 2 + 1];
            float go0 = acc[mi][3][b2 * 2],     go1 = acc[mi][3][b2 * 2 + 1];
            float cn0 = sigmoidf_(gf0 + bf0) * cold.x
                      + sigmoidf_(gi0 + bi0) * tanhf(gg0 + bg0);
            float cn1 = sigmoidf_(gf1 + bf1) * cold.y
                      + sigmoidf_(gi1 + bi1) * tanhf(gg1 + bg1);
            float h0 = sigmoidf_(go0 + bo0) * tanhf(cn0);
            float h1 = sigmoidf_(go1 + bo1) * tanhf(cn1);
            *(float2*)&g_c[cidx] = make_float2(cn0, cn1);
            *(float2*)&g_hf[cidx] = make_float2(h0, h1);
            float hh0 = __bfloat162float(__float2bfloat16(h0));
            float hh1 = __bfloat162float(__float2bfloat16(h1));
            uint32_t off = aoff(mrow, kk0);
            *(uint32_t*)(th + off) = bpack(hh0, hh1);
            *(uint32_t*)(tl + off) = bpack(h0 - hh0, h1 - hh1);
        }
    }
}

// ---------------------------------------------------------------------------
// Key pass (batch 8): split-K SIMT GEMM + cell update
// ---------------------------------------------------------------------------
#define KSPLIT 8
#define KSLICE 132
__global__ void key_gemm(const float* __restrict__ key,
                         const float* __restrict__ Wih,
                         const float* __restrict__ Whh,
                         int t, int p)
{
    __shared__ float hs[KBATCH][KSLICE];
    const int cb = blockIdx.x;
    const int ks = blockIdx.y;
    const int tid = threadIdx.x;
    const int k0 = ks * KSLICE;
    const int k1 = min(k0 + KSLICE, HDIM + DD);

    for (int i = tid; i < KBATCH * KSLICE; i += 256) {
        int mm = i / KSLICE, kk = k0 + i % KSLICE;
        float v = 0.f;
        if (kk < HDIM) v = g_hk[p][mm * HDIM + kk];
        else if (kk < HDIM + DD) v = key[(size_t)(mm * TT + t) * DD + (kk - HDIM)];
        hs[mm][i % KSLICE] = v;
    }
    __syncthreads();

    const int colx = tid & 31, mm = tid >> 5;
    const int col = cb * 32 + colx;
    float acc = 0.f;
    for (int kk = k0; kk < k1; kk++) {
        float w = (kk < HDIM) ? Whh[(size_t)kk * GDIM + col]
                              : Wih[(size_t)(kk - HDIM) * GDIM + col];
        acc += hs[mm][kk - k0] * w;
    }
    atomicAdd(&g_gk[mm][col], acc);
}

__global__ void key_cell(const float* __restrict__ bias, int p)
{
    int i = blockIdx.x * blockDim.x + threadIdx.x;
    if (i >= KBATCH * HDIM) return;
    int mm = i >> 10, n = i & (HDIM - 1);
    float gi = g_gk[mm][n] + bias[n];
    float gf = g_gk[mm][HDIM + n] + bias[HDIM + n];
    float gg = g_gk[mm][2 * HDIM + n] + bias[2 * HDIM + n];
    float go = g_gk[mm][3 * HDIM + n] + bias[3 * HDIM + n];
    g_gk[mm][n] = 0.f; g_gk[mm][HDIM + n] = 0.f;
    g_gk[mm][2 * HDIM + n] = 0.f; g_gk[mm][3 * HDIM + n] = 0.f;
    float cold = g_ck[mm * HDIM + n];
    float cn = sigmoidf_(gf) * cold + sigmoidf_(gi) * tanhf(gg);
    g_ck[mm * HDIM + n] = cn;
    g_hk[1 - p][mm * HDIM + n] = sigmoidf_(go) * tanhf(cn);
}

__global__ void key_init()
{
    int i = blockIdx.x * blockDim.x + threadIdx.x;
    if (i < KBATCH * HDIM) { g_hk[0][i] = 0.f; g_ck[i] = 0.f; }
    if (i < KBATCH * GDIM) g_gk[i / GDIM][i % GDIM] = 0.f;
}

__global__ void key_mean(int p)
{
    int n = blockIdx.x * blockDim.x + threadIdx.x;
    if (n < HDIM) {
        float sh = 0.f, sc = 0.f;
        for (int m = 0; m < KBATCH; m++) {
            sh += g_hk[p][m * HDIM + n];
            sc += g_ck[m * HDIM + n];
        }
        g_h0[n] = sh * (1.0f / KBATCH);
        g_c0[n] = sc * (1.0f / KBATCH);
    }
}

// broadcast h0/c0 into A tiles + c
__global__ void bcast_init()
{
    int mb = blockIdx.x, ch = blockIdx.y;
    int r = threadIdx.x;
    int m = mb * 128 + r;
    char* th = (char*)&g_Ah[0][mb][ch][0];
    char* tl = (char*)&g_Al[0][mb][ch][0];
#pragma unroll
    for (int kk = 0; kk < KC; kk += 2) {
        int n = ch * KC + kk;
        float v0 = g_h0[n], v1 = g_h0[n + 1];
        float h0 = __bfloat162float(__float2bfloat16(v0));
        float h1 = __bfloat162float(__float2bfloat16(v1));
        uint32_t off = aoff(r, kk);
        *(uint32_t*)(th + off) = bpack(h0, h1);
        *(uint32_t*)(tl + off) = bpack(v0 - h0, v1 - h1);
        *(float2*)&g_c[(size_t)m * HDIM + n] = make_float2(g_c0[n], g_c0[n + 1]);
    }
}

// ---------------------------------------------------------------------------
__global__ void classify(const float* __restrict__ Wcls,
                         const float* __restrict__ bcls,
                         float* __restrict__ out)
{
    int gw = (blockIdx.x * blockDim.x + threadIdx.x) >> 5;
    int lane = threadIdx.x & 31;
    if (gw >= BB) return;
    const float* hr = &g_hf[(size_t)gw * HDIM];
    float acc[10];
#pragma unroll
    for (int c = 0; c < 10; c++) acc[c] = 0.f;
    for (int k = lane; k < HDIM; k += 32) {
        float hv = hr[k];
#pragma unroll
        for (int c = 0; c < 10; c++) acc[c] += hv * Wcls[k * 10 + c];
    }
#pragma unroll
    for (int c = 0; c < 10; c++) {
#pragma unroll
        for (int off = 16; off > 0; off >>= 1)
            acc[c] += __shfl_down_sync(0xffffffffu, acc[c], off);
    }
    if (lane == 0) {
#pragma unroll
        for (int c = 0; c < 10; c++)
            out[(size_t)gw * 10 + c] = acc[c] + bcls[c];
    }
}

// ---------------------------------------------------------------------------
extern "C" void kernel_launch(void* const* d_in, const int* in_sizes, int n_in,
                              void* d_out, int out_size)
{
    const float* x    = (const float*)d_in[0];
    const float* key  = (const float*)d_in[1];
    const float* Wih  = (const float*)d_in[2];
    const float* Whh  = (const float*)d_in[3];
    const float* b    = (const float*)d_in[4];
    const float* Wcls = (const float*)d_in[5];
    const float* bcls = (const float*)d_in[6];
    float* out = (float*)d_out;

    cudaFuncSetAttribute(data_step, cudaFuncAttributeMaxDynamicSharedMemorySize,
                         SMEM_DATA);

    prep_W<<<dim3(CPT, NBK), 256>>>(Wih, Whh);
    prep_x<<<dim3(MBK, TT), 128>>>(x);

    key_init<<<(KBATCH * GDIM + 255) / 256, 256>>>();
    for (int t = 0; t < TT; t++) {
        key_gemm<<<dim3(GDIM / 32, KSPLIT), 256>>>(key, Wih, Whh, t, t & 1);
        key_cell<<<(KBATCH * HDIM + 255) / 256, 256>>>(b, t & 1);
    }
    key_mean<<<(HDIM + 255) / 256, 256>>>(0);
    bcast_init<<<dim3(MBK, 16), 128>>>();

    dim3 grid(NBK, MBK);
    for (int t = 0; t < TT; t++)
        data_step<<<grid, 256, SMEM_DATA>>>(b, t, t & 1);

    classify<<<BB / 8, 256>>>(Wcls, bcls, out);
}

// round 7
// speedup vs baseline: 2.9782x; 1.0038x over previous
#include <cuda_runtime.h>
#include <cuda_bf16.h>
#include <cstdint>
#include <math.h>

#define HDIM 1024
#define GDIM 4096
#define TT 28
#define DD 28
#define BB 4096
#define KBATCH 8

// GEMM geometry (per data step): C[4096 x 4096gates] = A[4096 x K'] B[K' x 4096]
// K' = 3 terms x 17 chunks x 64 = 3264 (terms: AhiBhi, AhiBlo, AloBhi)
#define KC 64
#define CPT 17            // chunks per term (16 h-chunks + 1 x-chunk)
#define CHUNKS 51         // 3*CPT
#define NSTAGE 3
#define TILE_BYTES 16384  // 128 x 64 bf16
#define STAGE_BYTES 32768 // A tile + B tile
#define SMEM_DATA (NSTAGE * STAGE_BYTES)
#define MBK 32            // 4096/128 M-blocks
#define NBK 32            // 1024/32 out-blocks (128 gate-cols per CTA)

// ---------------- persistent scratch ----------------
__device__ __nv_bfloat16 g_Wh[NBK][CPT][8192];
__device__ __nv_bfloat16 g_Wl[NBK][CPT][8192];
__device__ __nv_bfloat16 g_Ah[2][MBK][16][8192];   // h tiles, ping-pong
__device__ __nv_bfloat16 g_Al[2][MBK][16][8192];
__device__ __nv_bfloat16 g_xh[TT][MBK][8192];
__device__ __nv_bfloat16 g_xl[TT][MBK][8192];
__device__ float g_c[(size_t)BB * HDIM];
__device__ float g_hf[(size_t)BB * HDIM];
__device__ float g_hk[2][KBATCH * HDIM];
__device__ float g_ck[KBATCH * HDIM];
__device__ float g_gk[KBATCH][GDIM];
__device__ float g_h0[HDIM];
__device__ float g_c0[HDIM];

// ---------------- helpers ----------------
__device__ __forceinline__ float sigmoidf_(float x) { return 1.0f / (1.0f + __expf(-x)); }

// swizzled byte offset within a 128x64 bf16 tile (128B rows, SW128 16B groups)
__device__ __forceinline__ uint32_t aoff(int row, int kk) {
    return (uint32_t)(row * 128 + ((((kk >> 3) ^ row) & 7) << 4) + (kk & 7) * 2);
}

__device__ __forceinline__ uint32_t smem_u32(const void* p) {
    uint32_t a;
    asm("{ .reg .u64 t; cvta.to.shared.u64 t, %1; cvt.u32.u64 %0, t; }" : "=r"(a) : "l"(p));
    return a;
}

__device__ __forceinline__ uint32_t bpack(float v0, float v1) {
    __nv_bfloat162 p = __floats2bfloat162_rn(v0, v1);
    return *(uint32_t*)&p;
}

#define CP_ASYNC16(dst, src) \
    asm volatile("cp.async.cg.shared.global [%0], [%1], 16;" :: "r"(dst), "l"(src))
#define CP_COMMIT() asm volatile("cp.async.commit_group;" ::: "memory")
#define CP_WAIT2()  asm volatile("cp.async.wait_group 2;" ::: "memory")

#define LDMX4(r0, r1, r2, r3, addr) \
    asm volatile("ldmatrix.sync.aligned.m8n8.x4.shared.b16 {%0,%1,%2,%3}, [%4];" \
        : "=r"(r0), "=r"(r1), "=r"(r2), "=r"(r3) : "r"(addr))
#define LDMX2(r0, r1, addr) \
    asm volatile("ldmatrix.sync.aligned.m8n8.x2.shared.b16 {%0,%1}, [%2];" \
        : "=r"(r0), "=r"(r1) : "r"(addr))
#define MMA16816(d, a, b0, b1) \
    asm volatile("mma.sync.aligned.m16n8k16.row.col.f32.bf16.bf16.f32 " \
        "{%0,%1,%2,%3},{%4,%5,%6,%7},{%8,%9},{%0,%1,%2,%3};" \
        : "+f"((d)[0]), "+f"((d)[1]), "+f"((d)[2]), "+f"((d)[3]) \
        : "r"((a)[0]), "r"((a)[1]), "r"((a)[2]), "r"((a)[3]), "r"(b0), "r"(b1))

// ---------------------------------------------------------------------------
// prep: bf16 hi/lo split of weights into swizzled [n][k] tiles.
// B tile col layout (128): warp w (n>>5), gate ((n>>3)&3), out_local (n&7)
// -> W column = gate*1024 + nb*32 + w*8 + ol
// ---------------------------------------------------------------------------
__global__ void prep_W(const float* __restrict__ Wih, const float* __restrict__ Whh)
{
    int kc = blockIdx.x, nb = blockIdx.y;
    int n = threadIdx.x & 127, kh = threadIdx.x >> 7;
    int w = n >> 5, gate = (n >> 3) & 3, ol = n & 7;
    int col = gate * HDIM + nb * 32 + w * 8 + ol;
    char* th = (char*)&g_Wh[nb][kc][0];
    char* tl = (char*)&g_Wl[nb][kc][0];
#pragma unroll
    for (int kk = kh * 32; kk < kh * 32 + 32; kk += 2) {
        float v0, v1;
        if (kc < 16) {
            size_t kg = (size_t)(kc * 64 + kk);
            v0 = Whh[kg * GDIM + col];
            v1 = Whh[(kg + 1) * GDIM + col];
        } else {
            v0 = (kk < DD) ? Wih[(size_t)kk * GDIM + col] : 0.f;
            v1 = (kk + 1 < DD) ? Wih[(size_t)(kk + 1) * GDIM + col] : 0.f;
        }
        float h0 = __bfloat162float(__float2bfloat16(v0));
        float h1 = __bfloat162float(__float2bfloat16(v1));
        uint32_t off = aoff(n, kk);
        *(uint32_t*)(th + off) = bpack(h0, h1);
        *(uint32_t*)(tl + off) = bpack(v0 - h0, v1 - h1);
    }
}

__global__ void prep_x(const float* __restrict__ x)
{
    int mb = blockIdx.x, t = blockIdx.y;
    int r = threadIdx.x;
    int m = mb * 128 + r;
    char* th = (char*)&g_xh[t][mb][0];
    char* tl = (char*)&g_xl[t][mb][0];
#pragma unroll
    for (int kk = 0; kk < KC; kk += 2) {
        float v0 = (kk < DD) ? x[((size_t)m * TT + t) * DD + kk] : 0.f;
        float v1 = (kk + 1 < DD) ? x[((size_t)m * TT + t) * DD + kk + 1] : 0.f;
        float h0 = __bfloat162float(__float2bfloat16(v0));
        float h1 = __bfloat162float(__float2bfloat16(v1));
        uint32_t off = aoff(r, kk);
        *(uint32_t*)(th + off) = bpack(h0, h1);
        *(uint32_t*)(tl + off) = bpack(v0 - h0, v1 - h1);
    }
}

// ---------------------------------------------------------------------------
// Data step: bf16 mma.sync GEMM (3-term K-folded) + fused LSTM cell
// ---------------------------------------------------------------------------
__device__ __forceinline__ void load_chunk(uint32_t smb, int tid, int c,
                                           int t, int pp, int mb, int nb)
{
    if (c < CHUNKS) {
        int term = (c >= 2 * CPT) ? 2 : (c >= CPT ? 1 : 0);
        int kc = c - term * CPT;
        const char* as;
        if (kc == 16)
            as = (const char*)((term < 2) ? &g_xh[t][mb][0] : &g_xl[t][mb][0]);
        else
            as = (const char*)((term < 2) ? &g_Ah[pp][mb][kc][0] : &g_Al[pp][mb][kc][0]);
        const char* bs = (const char*)((term == 1) ? &g_Wl[nb][kc][0] : &g_Wh[nb][kc][0]);
        uint32_t dst = smb + (c % NSTAGE) * STAGE_BYTES;
        int o = tid * 16;
#pragma unroll
        for (int i = 0; i < 4; i++) {
            CP_ASYNC16(dst + o, as + o);
            CP_ASYNC16(dst + TILE_BYTES + o, bs + o);
            o += 4096;
        }
    }
    CP_COMMIT();
}

__global__ void __launch_bounds__(256, 2)
data_step(const float* __restrict__ bias, int t, int pp)
{
    extern __shared__ __align__(128) char sm[];
    const uint32_t smb = smem_u32(sm);
    const int tid = threadIdx.x, wid = tid >> 5, lane = tid & 31;
    const int nb = blockIdx.x, mb = blockIdx.y;
    const int mw = (wid >> 2) * 64;       // warp m offset
    const int nw = (wid & 3) * 32;        // warp n(col) offset

    float acc[4][4][4];
#pragma unroll
    for (int i = 0; i < 4; i++)
#pragma unroll
        for (int j = 0; j < 4; j++)
#pragma unroll
            for (int q = 0; q < 4; q++) acc[i][j][q] = 0.f;

    load_chunk(smb, tid, 0, t, pp, mb, nb);
    load_chunk(smb, tid, 1, t, pp, mb, nb);
    load_chunk(smb, tid, 2, t, pp, mb, nb);

    // precomputed lane geometry
    const int a_row7 = lane & 7;
    const int a_sel8 = ((lane >> 3) & 1) * 8;
    const int a_ghalf = lane >> 4;
    const int ln = lane & 15;
    const int b_n7 = ln & 7;
    const int b_ghalf = ln >> 3;

    for (int c = 0; c < CHUNKS; c++) {
        CP_WAIT2();
        __syncthreads();
        uint32_t sa = smb + (c % NSTAGE) * STAGE_BYTES;
        uint32_t sbB = sa + TILE_BYTES;
#pragma unroll
        for (int kb = 0; kb < 4; kb++) {
            uint32_t a[4][4];
#pragma unroll
            for (int mi = 0; mi < 4; mi++) {
                int row = mw + mi * 16 + a_sel8 + a_row7;
                int grp = 2 * kb + a_ghalf;
                uint32_t ad = sa + row * 128 + (((grp ^ row) & 7) << 4);
                LDMX4(a[mi][0], a[mi][1], a[mi][2], a[mi][3], ad);
            }
#pragma unroll
            for (int ni = 0; ni < 4; ni++) {
                int n = nw + ni * 8 + b_n7;
                int grp = 2 * kb + b_ghalf;
                uint32_t bd = sbB + n * 128 + (((grp ^ n) & 7) << 4);
                uint32_t b0, b1;
                LDMX2(b0, b1, bd);
#pragma unroll
                for (int mi = 0; mi < 4; mi++)
                    MMA16816(acc[mi][ni], a[mi], b0, b1);
            }
        }
        __syncthreads();
        load_chunk(smb, tid, c + NSTAGE, t, pp, mb, nb);
    }

    // ---- fused LSTM cell epilogue ----
    // thread owns rows mw+mi*16+(lane>>2)+{0,8}, outs o0,o0+1 with all 4 gates
    const int r4 = lane >> 2;
    const int o0 = nb * 32 + (wid & 3) * 8 + (lane & 3) * 2;
    const int chunk = nb >> 1;
    const int kk0 = o0 & 63;
    float bi0 = bias[o0],            bi1 = bias[o0 + 1];
    float bf0 = bias[HDIM + o0],     bf1 = bias[HDIM + o0 + 1];
    float bg0 = bias[2*HDIM + o0],   bg1 = bias[2*HDIM + o0 + 1];
    float bo0 = bias[3*HDIM + o0],   bo1 = bias[3*HDIM + o0 + 1];
    char* th = (char*)&g_Ah[pp ^ 1][mb][chunk][0];
    char* tl = (char*)&g_Al[pp ^ 1][mb][chunk][0];

#pragma unroll
    for (int mi = 0; mi < 4; mi++) {
#pragma unroll
        for (int b2 = 0; b2 < 2; b2++) {
            int mrow = mw + mi * 16 + r4 + b2 * 8;
            int m = mb * 128 + mrow;
            size_t cidx = (size_t)m * HDIM + o0;
            float2 cold = *(float2*)&g_c[cidx];
            float gi0 = acc[mi][0][b2 * 2],     gi1 = acc[mi][0][b2 * 2 + 1];
            float gf0 = acc[mi][1][b2 * 2],     gf1 = acc[mi][1][b2 * 2 + 1];
            float gg0 = acc[mi][2][b2 * 2],     gg1 = acc[mi][2][b2 * 2 + 1];
            float go0 = acc[mi][3][b2 * 2],     go1 = acc[mi][3][b2 * 2 + 1];
            float cn0 = sigmoidf_(gf0 + bf0) * cold.x
                      + sigmoidf_(gi0 + bi0) * tanhf(gg0 + bg0);
            float cn1 = sigmoidf_(gf1 + bf1) * cold.y
                      + sigmoidf_(gi1 + bi1) * tanhf(gg1 + bg1);
            float h0 = sigmoidf_(go0 + bo0) * tanhf(cn0);
            float h1 = sigmoidf_(go1 + bo1) * tanhf(cn1);
            *(float2*)&g_c[cidx] = make_float2(cn0, cn1);
            *(float2*)&g_hf[cidx] = make_float2(h0, h1);
            float hh0 = __bfloat162float(__float2bfloat16(h0));
            float hh1 = __bfloat162float(__float2bfloat16(h1));
            uint32_t off = aoff(mrow, kk0);
            *(uint32_t*)(th + off) = bpack(hh0, hh1);
            *(uint32_t*)(tl + off) = bpack(h0 - hh0, h1 - hh1);
        }
    }
}

// ---------------------------------------------------------------------------
// Key pass (batch 8): split-K SIMT GEMM + cell update
// ---------------------------------------------------------------------------
#define KSPLIT 8
#define KSLICE 132
__global__ void key_gemm(const float* __restrict__ key,
                         const float* __restrict__ Wih,
                         const float* __restrict__ Whh,
                         int t, int p)
{
    __shared__ float hs[KBATCH][KSLICE];
    const int cb = blockIdx.x;
    const int ks = blockIdx.y;
    const int tid = threadIdx.x;
    const int k0 = ks * KSLICE;
    const int k1 = min(k0 + KSLICE, HDIM + DD);

    for (int i = tid; i < KBATCH * KSLICE; i += 256) {
        int mm = i / KSLICE, kk = k0 + i % KSLICE;
        float v = 0.f;
        if (kk < HDIM) v = g_hk[p][mm * HDIM + kk];
        else if (kk < HDIM + DD) v = key[(size_t)(mm * TT + t) * DD + (kk - HDIM)];
        hs[mm][i % KSLICE] = v;
    }
    __syncthreads();

    const int colx = tid & 31, mm = tid >> 5;
    const int col = cb * 32 + colx;
    float acc = 0.f;
    for (int kk = k0; kk < k1; kk++) {
        float w = (kk < HDIM) ? Whh[(size_t)kk * GDIM + col]
                              : Wih[(size_t)(kk - HDIM) * GDIM + col];
        acc += hs[mm][kk - k0] * w;
    }
    atomicAdd(&g_gk[mm][col], acc);
}

__global__ void key_cell(const float* __restrict__ bias, int p)
{
    int i = blockIdx.x * blockDim.x + threadIdx.x;
    if (i >= KBATCH * HDIM) return;
    int mm = i >> 10, n = i & (HDIM - 1);
    float gi = g_gk[mm][n] + bias[n];
    float gf = g_gk[mm][HDIM + n] + bias[HDIM + n];
    float gg = g_gk[mm][2 * HDIM + n] + bias[2 * HDIM + n];
    float go = g_gk[mm][3 * HDIM + n] + bias[3 * HDIM + n];
    g_gk[mm][n] = 0.f; g_gk[mm][HDIM + n] = 0.f;
    g_gk[mm][2 * HDIM + n] = 0.f; g_gk[mm][3 * HDIM + n] = 0.f;
    float cold = g_ck[mm * HDIM + n];
    float cn = sigmoidf_(gf) * cold + sigmoidf_(gi) * tanhf(gg);
    g_ck[mm * HDIM + n] = cn;
    g_hk[1 - p][mm * HDIM + n] = sigmoidf_(go) * tanhf(cn);
}

__global__ void key_init()
{
    int i = blockIdx.x * blockDim.x + threadIdx.x;
    if (i < KBATCH * HDIM) { g_hk[0][i] = 0.f; g_ck[i] = 0.f; }
    if (i < KBATCH * GDIM) g_gk[i / GDIM][i % GDIM] = 0.f;
}

__global__ void key_mean(int p)
{
    int n = blockIdx.x * blockDim.x + threadIdx.x;
    if (n < HDIM) {
        float sh = 0.f, sc = 0.f;
        for (int m = 0; m < KBATCH; m++) {
            sh += g_hk[p][m * HDIM + n];
            sc += g_ck[m * HDIM + n];
        }
        g_h0[n] = sh * (1.0f / KBATCH);
        g_c0[n] = sc * (1.0f / KBATCH);
    }
}

// broadcast h0/c0 into A tiles + c
__global__ void bcast_init()
{
    int mb = blockIdx.x, ch = blockIdx.y;
    int r = threadIdx.x;
    int m = mb * 128 + r;
    char* th = (char*)&g_Ah[0][mb][ch][0];
    char* tl = (char*)&g_Al[0][mb][ch][0];
#pragma unroll
    for (int kk = 0; kk < KC; kk += 2) {
        int n = ch * KC + kk;
        float v0 = g_h0[n], v1 = g_h0[n + 1];
        float h0 = __bfloat162float(__float2bfloat16(v0));
        float h1 = __bfloat162float(__float2bfloat16(v1));
        uint32_t off = aoff(r, kk);
        *(uint32_t*)(th + off) = bpack(h0, h1);
        *(uint32_t*)(tl + off) = bpack(v0 - h0, v1 - h1);
        *(float2*)&g_c[(size_t)m * HDIM + n] = make_float2(g_c0[n], g_c0[n + 1]);
    }
}

// ---------------------------------------------------------------------------
__global__ void classify(const float* __restrict__ Wcls,
                         const float* __restrict__ bcls,
                         float* __restrict__ out)
{
    int gw = (blockIdx.x * blockDim.x + threadIdx.x) >> 5;
    int lane = threadIdx.x & 31;
    if (gw >= BB) return;
    const float* hr = &g_hf[(size_t)gw * HDIM];
    float acc[10];
#pragma unroll
    for (int c = 0; c < 10; c++) acc[c] = 0.f;
    for (int k = lane; k < HDIM; k += 32) {
        float hv = hr[k];
#pragma unroll
        for (int c = 0; c < 10; c++) acc[c] += hv * Wcls[k * 10 + c];
    }
#pragma unroll
    for (int c = 0; c < 10; c++) {
#pragma unroll
        for (int off = 16; off > 0; off >>= 1)
            acc[c] += __shfl_down_sync(0xffffffffu, acc[c], off);
    }
    if (lane == 0) {
#pragma unroll
        for (int c = 0; c < 10; c++)
            out[(size_t)gw * 10 + c] = acc[c] + bcls[c];
    }
}

// ---------------------------------------------------------------------------
extern "C" void kernel_launch(void* const* d_in, const int* in_sizes, int n_in,
                              void* d_out, int out_size)
{
    const float* x    = (const float*)d_in[0];
    const float* key  = (const float*)d_in[1];
    const float* Wih  = (const float*)d_in[2];
    const float* Whh  = (const float*)d_in[3];
    const float* b    = (const float*)d_in[4];
    const float* Wcls = (const float*)d_in[5];
    const float* bcls = (const float*)d_in[6];
    float* out = (float*)d_out;

    cudaFuncSetAttribute(data_step, cudaFuncAttributeMaxDynamicSharedMemorySize,
                         SMEM_DATA);

    prep_W<<<dim3(CPT, NBK), 256>>>(Wih, Whh);
    prep_x<<<dim3(MBK, TT), 128>>>(x);

    key_init<<<(KBATCH * GDIM + 255) / 256, 256>>>();
    for (int t = 0; t < TT; t++) {
        key_gemm<<<dim3(GDIM / 32, KSPLIT), 256>>>(key, Wih, Whh, t, t & 1);
        key_cell<<<(KBATCH * HDIM + 255) / 256, 256>>>(b, t & 1);
    }
    key_mean<<<(HDIM + 255) / 256, 256>>>(0);
    bcast_init<<<dim3(MBK, 16), 128>>>();

    dim3 grid(NBK, MBK);
    for (int t = 0; t < TT; t++)
        data_step<<<grid, 256, SMEM_DATA>>>(b, t, t & 1);

    classify<<<BB / 8, 256>>>(Wcls, bcls, out);
}

// round 8
// speedup vs baseline: 3.0238x; 1.0153x over previous
#include <cuda_runtime.h>
#include <cuda_bf16.h>
#include <cstdint>
#include <math.h>

#define HDIM 1024
#define GDIM 4096
#define TT 28
#define DD 28
#define BB 4096
#define KBATCH 8

// GEMM geometry: C[4096 x 4096gates] = sum of 3 bf16 terms, fused per K-chunk
#define KC 64
#define CPT 17            // K-chunks (16 h-chunks + 1 x-chunk)
#define NSTAGE 3
#define TILE_BYTES 16384  // 128 x 64 bf16
#define STAGE_BYTES 65536 // Ah + Al + Bh + Bl
#define SMEM_DATA (NSTAGE * STAGE_BYTES)   // 192 KB
#define MBK 32            // 4096/128 M-blocks
#define NBK 32            // 1024/32 out-blocks (128 gate-cols per CTA)

// ---------------- persistent scratch ----------------
__device__ __nv_bfloat16 g_Wh[NBK][CPT][8192];
__device__ __nv_bfloat16 g_Wl[NBK][CPT][8192];
__device__ __nv_bfloat16 g_Ah[2][MBK][16][8192];   // h tiles, ping-pong
__device__ __nv_bfloat16 g_Al[2][MBK][16][8192];
__device__ __nv_bfloat16 g_xh[TT][MBK][8192];
__device__ __nv_bfloat16 g_xl[TT][MBK][8192];
__device__ float g_c[(size_t)BB * HDIM];
__device__ float g_hf[(size_t)BB * HDIM];
__device__ float g_hk[2][KBATCH * HDIM];
__device__ float g_ck[KBATCH * HDIM];
__device__ float g_gk[KBATCH][GDIM];
__device__ float g_h0[HDIM];
__device__ float g_c0[HDIM];

// ---------------- helpers ----------------
__device__ __forceinline__ float sigmoidf_(float x) { return 1.0f / (1.0f + __expf(-x)); }

// swizzled byte offset within a 128x64 bf16 tile (128B rows, SW128 16B groups)
__device__ __forceinline__ uint32_t aoff(int row, int kk) {
    return (uint32_t)(row * 128 + ((((kk >> 3) ^ row) & 7) << 4) + (kk & 7) * 2);
}

__device__ __forceinline__ uint32_t smem_u32(const void* p) {
    uint32_t a;
    asm("{ .reg .u64 t; cvta.to.shared.u64 t, %1; cvt.u32.u64 %0, t; }" : "=r"(a) : "l"(p));
    return a;
}

__device__ __forceinline__ uint32_t bpack(float v0, float v1) {
    __nv_bfloat162 p = __floats2bfloat162_rn(v0, v1);
    return *(uint32_t*)&p;
}

#define CP_ASYNC16(dst, src) \
    asm volatile("cp.async.cg.shared.global [%0], [%1], 16;" :: "r"(dst), "l"(src))
#define CP_COMMIT() asm volatile("cp.async.commit_group;" ::: "memory")
#define CP_WAIT2()  asm volatile("cp.async.wait_group 2;" ::: "memory")

#define LDMX4(r0, r1, r2, r3, addr) \
    asm volatile("ldmatrix.sync.aligned.m8n8.x4.shared.b16 {%0,%1,%2,%3}, [%4];" \
        : "=r"(r0), "=r"(r1), "=r"(r2), "=r"(r3) : "r"(addr))
#define LDMX2(r0, r1, addr) \
    asm volatile("ldmatrix.sync.aligned.m8n8.x2.shared.b16 {%0,%1}, [%2];" \
        : "=r"(r0), "=r"(r1) : "r"(addr))
#define MMA16816(d, a, b0, b1) \
    asm volatile("mma.sync.aligned.m16n8k16.row.col.f32.bf16.bf16.f32 " \
        "{%0,%1,%2,%3},{%4,%5,%6,%7},{%8,%9},{%0,%1,%2,%3};" \
        : "+f"((d)[0]), "+f"((d)[1]), "+f"((d)[2]), "+f"((d)[3]) \
        : "r"((a)[0]), "r"((a)[1]), "r"((a)[2]), "r"((a)[3]), "r"(b0), "r"(b1))

// ---------------------------------------------------------------------------
// prep: bf16 hi/lo split of weights into swizzled [n][k] tiles.
// B tile col layout (128): warp w (n>>5), gate ((n>>3)&3), out_local (n&7)
// -> W column = gate*1024 + nb*32 + w*8 + ol
// ---------------------------------------------------------------------------
__global__ void prep_W(const float* __restrict__ Wih, const float* __restrict__ Whh)
{
    int kc = blockIdx.x, nb = blockIdx.y;
    int n = threadIdx.x & 127, kh = threadIdx.x >> 7;
    int w = n >> 5, gate = (n >> 3) & 3, ol = n & 7;
    int col = gate * HDIM + nb * 32 + w * 8 + ol;
    char* th = (char*)&g_Wh[nb][kc][0];
    char* tl = (char*)&g_Wl[nb][kc][0];
#pragma unroll
    for (int kk = kh * 32; kk < kh * 32 + 32; kk += 2) {
        float v0, v1;
        if (kc < 16) {
            size_t kg = (size_t)(kc * 64 + kk);
            v0 = Whh[kg * GDIM + col];
            v1 = Whh[(kg + 1) * GDIM + col];
        } else {
            v0 = (kk < DD) ? Wih[(size_t)kk * GDIM + col] : 0.f;
            v1 = (kk + 1 < DD) ? Wih[(size_t)(kk + 1) * GDIM + col] : 0.f;
        }
        float h0 = __bfloat162float(__float2bfloat16(v0));
        float h1 = __bfloat162float(__float2bfloat16(v1));
        uint32_t off = aoff(n, kk);
        *(uint32_t*)(th + off) = bpack(h0, h1);
        *(uint32_t*)(tl + off) = bpack(v0 - h0, v1 - h1);
    }
}

__global__ void prep_x(const float* __restrict__ x)
{
    int mb = blockIdx.x, t = blockIdx.y;
    int r = threadIdx.x;
    int m = mb * 128 + r;
    char* th = (char*)&g_xh[t][mb][0];
    char* tl = (char*)&g_xl[t][mb][0];
#pragma unroll
    for (int kk = 0; kk < KC; kk += 2) {
        float v0 = (kk < DD) ? x[((size_t)m * TT + t) * DD + kk] : 0.f;
        float v1 = (kk + 1 < DD) ? x[((size_t)m * TT + t) * DD + kk + 1] : 0.f;
        float h0 = __bfloat162float(__float2bfloat16(v0));
        float h1 = __bfloat162float(__float2bfloat16(v1));
        uint32_t off = aoff(r, kk);
        *(uint32_t*)(th + off) = bpack(h0, h1);
        *(uint32_t*)(tl + off) = bpack(v0 - h0, v1 - h1);
    }
}

// ---------------------------------------------------------------------------
// Data step: bf16 mma.sync GEMM, 3 terms fused per K-chunk + fused LSTM cell
// Stage layout: [Ah 16K][Al 16K][Bh 16K][Bl 16K]
// ---------------------------------------------------------------------------
__device__ __forceinline__ void load_chunk(uint32_t smb, int tid, int c,
                                           int t, int pp, int mb, int nb)
{
    if (c < CPT) {
        const char* ah;
        const char* al;
        if (c == 16) { ah = (const char*)&g_xh[t][mb][0]; al = (const char*)&g_xl[t][mb][0]; }
        else         { ah = (const char*)&g_Ah[pp][mb][c][0]; al = (const char*)&g_Al[pp][mb][c][0]; }
        const char* bh = (const char*)&g_Wh[nb][c][0];
        const char* bl = (const char*)&g_Wl[nb][c][0];
        uint32_t dst = smb + (c % NSTAGE) * STAGE_BYTES;
        int o = tid * 16;
#pragma unroll
        for (int i = 0; i < 4; i++) {
            CP_ASYNC16(dst + o,                 ah + o);
            CP_ASYNC16(dst + TILE_BYTES + o,    al + o);
            CP_ASYNC16(dst + 2*TILE_BYTES + o,  bh + o);
            CP_ASYNC16(dst + 3*TILE_BYTES + o,  bl + o);
            o += 4096;
        }
    }
    CP_COMMIT();
}

__global__ void __launch_bounds__(256, 1)
data_step(const float* __restrict__ bias, int t, int pp)
{
    extern __shared__ __align__(128) char sm[];
    const uint32_t smb = smem_u32(sm);
    const int tid = threadIdx.x, wid = tid >> 5, lane = tid & 31;
    const int nb = blockIdx.x, mb = blockIdx.y;
    const int mw = (wid >> 2) * 64;       // warp m offset
    const int nw = (wid & 3) * 32;        // warp n(col) offset

    float acc[4][4][4];
#pragma unroll
    for (int i = 0; i < 4; i++)
#pragma unroll
        for (int j = 0; j < 4; j++)
#pragma unroll
            for (int q = 0; q < 4; q++) acc[i][j][q] = 0.f;

    load_chunk(smb, tid, 0, t, pp, mb, nb);
    load_chunk(smb, tid, 1, t, pp, mb, nb);
    load_chunk(smb, tid, 2, t, pp, mb, nb);

    // lane geometry (row/n low bits invariant across mi/ni steps of 16/8)
    const int a_row0 = mw + ((lane >> 3) & 1) * 8 + (lane & 7);   // + mi*16
    const int a_ghalf = lane >> 4;
    const int b_n0 = nw + (lane & 7);                              // + ni*8 (lanes 0-15)
    const int b_ghalf = (lane & 15) >> 3;

    for (int c = 0; c < CPT; c++) {
        CP_WAIT2();
        __syncthreads();
        uint32_t sAh = smb + (c % NSTAGE) * STAGE_BYTES;
        uint32_t sAl = sAh + TILE_BYTES;
        uint32_t sBh = sAh + 2 * TILE_BYTES;
        uint32_t sBl = sAh + 3 * TILE_BYTES;
#pragma unroll
        for (int kb = 0; kb < 4; kb++) {
            const int agrp = 2 * kb + a_ghalf;
            const uint32_t acsw = (uint32_t)(((agrp ^ a_row0) & 7) << 4);
            const int bgrp = 2 * kb + b_ghalf;
            const uint32_t bcsw = (uint32_t)(((bgrp ^ b_n0) & 7) << 4);

            uint32_t ah[4][4], bh[4][2], bl[4][2];
#pragma unroll
            for (int mi = 0; mi < 4; mi++) {
                uint32_t ad = sAh + (uint32_t)(a_row0 + mi * 16) * 128 + acsw;
                LDMX4(ah[mi][0], ah[mi][1], ah[mi][2], ah[mi][3], ad);
            }
#pragma unroll
            for (int ni = 0; ni < 4; ni++) {
                uint32_t brow = (uint32_t)(b_n0 + ni * 8) * 128;
                LDMX2(bh[ni][0], bh[ni][1], sBh + brow + bcsw);
                LDMX2(bl[ni][0], bl[ni][1], sBl + brow + bcsw);
            }
            // term 0: Ah * Bh ; term 1: Ah * Bl
#pragma unroll
            for (int ni = 0; ni < 4; ni++)
#pragma unroll
                for (int mi = 0; mi < 4; mi++) {
                    MMA16816(acc[mi][ni], ah[mi], bh[ni][0], bh[ni][1]);
                    MMA16816(acc[mi][ni], ah[mi], bl[ni][0], bl[ni][1]);
                }
            // term 2: Al * Bh (reuse ah regs)
            uint32_t al[4][4];
#pragma unroll
            for (int mi = 0; mi < 4; mi++) {
                uint32_t ad = sAl + (uint32_t)(a_row0 + mi * 16) * 128 + acsw;
                LDMX4(al[mi][0], al[mi][1], al[mi][2], al[mi][3], ad);
            }
#pragma unroll
            for (int ni = 0; ni < 4; ni++)
#pragma unroll
                for (int mi = 0; mi < 4; mi++)
                    MMA16816(acc[mi][ni], al[mi], bh[ni][0], bh[ni][1]);
        }
        __syncthreads();
        load_chunk(smb, tid, c + NSTAGE, t, pp, mb, nb);
    }

    // ---- fused LSTM cell epilogue ----
    const int r4 = lane >> 2;
    const int o0 = nb * 32 + (wid & 3) * 8 + (lane & 3) * 2;
    const int chunk = nb >> 1;
    const int kk0 = o0 & 63;
    float bi0 = bias[o0],            bi1 = bias[o0 + 1];
    float bf0 = bias[HDIM + o0],     bf1 = bias[HDIM + o0 + 1];
    float bg0 = bias[2*HDIM + o0],   bg1 = bias[2*HDIM + o0 + 1];
    float bo0 = bias[3*HDIM + o0],   bo1 = bias[3*HDIM + o0 + 1];
    char* th = (char*)&g_Ah[pp ^ 1][mb][chunk][0];
    char* tl = (char*)&g_Al[pp ^ 1][mb][chunk][0];

#pragma unroll
    for (int mi = 0; mi < 4; mi++) {
#pragma unroll
        for (int b2 = 0; b2 < 2; b2++) {
            int mrow = mw + mi * 16 + r4 + b2 * 8;
            int m = mb * 128 + mrow;
            size_t cidx = (size_t)m * HDIM + o0;
            float2 cold = *(float2*)&g_c[cidx];
            float gi0 = acc[mi][0][b2 * 2],     gi1 = acc[mi][0][b2 * 2 + 1];
            float gf0 = acc[mi][1][b2 * 2],     gf1 = acc[mi][1][b2 * 2 + 1];
            float gg0 = acc[mi][2][b2 * 2],     gg1 = acc[mi][2][b2 * 2 + 1];
            float go0 = acc[mi][3][b2 * 2],     go1 = acc[mi][3][b2 * 2 + 1];
            float cn0 = sigmoidf_(gf0 + bf0) * cold.x
                      + sigmoidf_(gi0 + bi0) * tanhf(gg0 + bg0);
            float cn1 = sigmoidf_(gf1 + bf1) * cold.y
                      + sigmoidf_(gi1 + bi1) * tanhf(gg1 + bg1);
            float h0 = sigmoidf_(go0 + bo0) * tanhf(cn0);
            float h1 = sigmoidf_(go1 + bo1) * tanhf(cn1);
            *(float2*)&g_c[cidx] = make_float2(cn0, cn1);
            *(float2*)&g_hf[cidx] = make_float2(h0, h1);
            float hh0 = __bfloat162float(__float2bfloat16(h0));
            float hh1 = __bfloat162float(__float2bfloat16(h1));
            uint32_t off = aoff(mrow, kk0);
            *(uint32_t*)(th + off) = bpack(hh0, hh1);
            *(uint32_t*)(tl + off) = bpack(h0 - hh0, h1 - hh1);
        }
    }
}

// ---------------------------------------------------------------------------
// Key pass (batch 8): split-K SIMT GEMM, one thread per column (all 8 rows)
// ---------------------------------------------------------------------------
#define KSPLIT 16
#define KSLICE 66
__global__ void key_gemm(const float* __restrict__ key,
                         const float* __restrict__ Wih,
                         const float* __restrict__ Whh,
                         int t, int p)
{
    __shared__ float hs[KBATCH][KSLICE];
    const int cb = blockIdx.x;   // 16 col-blocks of 256
    const int ks = blockIdx.y;   // 16 K-splits
    const int tid = threadIdx.x;
    const int k0 = ks * KSLICE;
    const int k1 = min(k0 + KSLICE, HDIM + DD);

    for (int i = tid; i < KBATCH * KSLICE; i += 256) {
        int mm = i / KSLICE, kk = k0 + i % KSLICE;
        float v = 0.f;
        if (kk < HDIM) v = g_hk[p][mm * HDIM + kk];
        else if (kk < HDIM + DD) v = key[(size_t)(mm * TT + t) * DD + (kk - HDIM)];
        hs[mm][i % KSLICE] = v;
    }
    __syncthreads();

    const int col = cb * 256 + tid;
    float acc[KBATCH];
#pragma unroll
    for (int mm = 0; mm < KBATCH; mm++) acc[mm] = 0.f;

    const int k1h = min(k1, HDIM);
    for (int kk = k0; kk < k1h; kk++) {
        float w = Whh[(size_t)kk * GDIM + col];
        int j = kk - k0;
#pragma unroll
        for (int mm = 0; mm < KBATCH; mm++) acc[mm] += hs[mm][j] * w;
    }
    for (int kk = max(k0, HDIM); kk < k1; kk++) {
        float w = Wih[(size_t)(kk - HDIM) * GDIM + col];
        int j = kk - k0;
#pragma unroll
        for (int mm = 0; mm < KBATCH; mm++) acc[mm] += hs[mm][j] * w;
    }
#pragma unroll
    for (int mm = 0; mm < KBATCH; mm++)
        atomicAdd(&g_gk[mm][col], acc[mm]);
}

__global__ void key_cell(const float* __restrict__ bias, int p)
{
    int i = blockIdx.x * blockDim.x + threadIdx.x;
    if (i >= KBATCH * HDIM) return;
    int mm = i >> 10, n = i & (HDIM - 1);
    float gi = g_gk[mm][n] + bias[n];
    float gf = g_gk[mm][HDIM + n] + bias[HDIM + n];
    float gg = g_gk[mm][2 * HDIM + n] + bias[2 * HDIM + n];
    float go = g_gk[mm][3 * HDIM + n] + bias[3 * HDIM + n];
    g_gk[mm][n] = 0.f; g_gk[mm][HDIM + n] = 0.f;
    g_gk[mm][2 * HDIM + n] = 0.f; g_gk[mm][3 * HDIM + n] = 0.f;
    float cold = g_ck[mm * HDIM + n];
    float cn = sigmoidf_(gf) * cold + sigmoidf_(gi) * tanhf(gg);
    g_ck[mm * HDIM + n] = cn;
    g_hk[1 - p][mm * HDIM + n] = sigmoidf_(go) * tanhf(cn);
}

__global__ void key_init()
{
    int i = blockIdx.x * blockDim.x + threadIdx.x;
    if (i < KBATCH * HDIM) { g_hk[0][i] = 0.f; g_ck[i] = 0.f; }
    if (i < KBATCH * GDIM) g_gk[i / GDIM][i % GDIM] = 0.f;
}

__global__ void key_mean(int p)
{
    int n = blockIdx.x * blockDim.x + threadIdx.x;
    if (n < HDIM) {
        float sh = 0.f, sc = 0.f;
        for (int m = 0; m < KBATCH; m++) {
            sh += g_hk[p][m * HDIM + n];
            sc += g_ck[m * HDIM + n];
        }
        g_h0[n] = sh * (1.0f / KBATCH);
        g_c0[n] = sc * (1.0f / KBATCH);
    }
}

// broadcast h0/c0 into A tiles + c
__global__ void bcast_init()
{
    int mb = blockIdx.x, ch = blockIdx.y;
    int r = threadIdx.x;
    int m = mb * 128 + r;
    char* th = (char*)&g_Ah[0][mb][ch][0];
    char* tl = (char*)&g_Al[0][mb][ch][0];
#pragma unroll
    for (int kk = 0; kk < KC; kk += 2) {
        int n = ch * KC + kk;
        float v0 = g_h0[n], v1 = g_h0[n + 1];
        float h0 = __bfloat162float(__float2bfloat16(v0));
        float h1 = __bfloat162float(__float2bfloat16(v1));
        uint32_t off = aoff(r, kk);
        *(uint32_t*)(th + off) = bpack(h0, h1);
        *(uint32_t*)(tl + off) = bpack(v0 - h0, v1 - h1);
        *(float2*)&g_c[(size_t)m * HDIM + n] = make_float2(g_c0[n], g_c0[n + 1]);
    }
}

// ---------------------------------------------------------------------------
__global__ void classify(const float* __restrict__ Wcls,
                         const float* __restrict__ bcls,
                         float* __restrict__ out)
{
    int gw = (blockIdx.x * blockDim.x + threadIdx.x) >> 5;
    int lane = threadIdx.x & 31;
    if (gw >= BB) return;
    const float* hr = &g_hf[(size_t)gw * HDIM];
    float acc[10];
#pragma unroll
    for (int c = 0; c < 10; c++) acc[c] = 0.f;
    for (int k = lane; k < HDIM; k += 32) {
        float hv = hr[k];
#pragma unroll
        for (int c = 0; c < 10; c++) acc[c] += hv * Wcls[k * 10 + c];
    }
#pragma unroll
    for (int c = 0; c < 10; c++) {
#pragma unroll
        for (int off = 16; off > 0; off >>= 1)
            acc[c] += __shfl_down_sync(0xffffffffu, acc[c], off);
    }
    if (lane == 0) {
#pragma unroll
        for (int c = 0; c < 10; c++)
            out[(size_t)gw * 10 + c] = acc[c] + bcls[c];
    }
}

// ---------------------------------------------------------------------------
extern "C" void kernel_launch(void* const* d_in, const int* in_sizes, int n_in,
                              void* d_out, int out_size)
{
    const float* x    = (const float*)d_in[0];
    const float* key  = (const float*)d_in[1];
    const float* Wih  = (const float*)d_in[2];
    const float* Whh  = (const float*)d_in[3];
    const float* b    = (const float*)d_in[4];
    const float* Wcls = (const float*)d_in[5];
    const float* bcls = (const float*)d_in[6];
    float* out = (float*)d_out;

    cudaFuncSetAttribute(data_step, cudaFuncAttributeMaxDynamicSharedMemorySize,
                         SMEM_DATA);

    prep_W<<<dim3(CPT, NBK), 256>>>(Wih, Whh);
    prep_x<<<dim3(MBK, TT), 128>>>(x);

    key_init<<<(KBATCH * GDIM + 255) / 256, 256>>>();
    for (int t = 0; t < TT; t++) {
        key_gemm<<<dim3(GDIM / 256, KSPLIT), 256>>>(key, Wih, Whh, t, t & 1);
        key_cell<<<(KBATCH * HDIM + 255) / 256, 256>>>(b, t & 1);
    }
    key_mean<<<(HDIM + 255) / 256, 256>>>(0);
    bcast_init<<<dim3(MBK, 16), 128>>>();

    dim3 grid(NBK, MBK);
    for (int t = 0; t < TT; t++)
        data_step<<<grid, 256, SMEM_DATA>>>(b, t, t & 1);

    classify<<<BB / 8, 256>>>(Wcls, bcls, out);
}

// round 9
// speedup vs baseline: 4.3431x; 1.4363x over previous
#include <cuda_runtime.h>
#include <cuda_fp16.h>
#include <cstdint>
#include <math.h>

#define HDIM 1024
#define GDIM 4096
#define TT 28
#define DD 28
#define BB 4096
#define KBATCH 8

// GEMM: C[4096 x 4096gates], fp16 2-term (AhBh + AhBl), per-K-chunk fused
#define KC 64
#define CPT 17            // K-chunks (16 h-chunks + 1 x-chunk)
#define NSTAGE 4
#define TILE_BYTES 16384  // 128 x 64 fp16
#define STAGE_BYTES 49152 // Ah + Bh + Bl
#define SMEM_DATA (NSTAGE * STAGE_BYTES)   // 192 KB
#define MBK 32            // 4096/128 M-blocks
#define NBK 32            // 1024/32 out-blocks (128 gate-cols per CTA)

// ---------------- persistent scratch ----------------
__device__ __half g_Wh[NBK][CPT][8192];
__device__ __half g_Wl[NBK][CPT][8192];
__device__ __half g_Ah[2][MBK][16][8192];   // h tiles (fp16 rounded), ping-pong
__device__ __half g_xh[TT][MBK][8192];
__device__ float g_c[(size_t)BB * HDIM];
__device__ float g_hf[(size_t)BB * HDIM];
__device__ float g_hk[2][KBATCH * HDIM];
__device__ float g_ck[KBATCH * HDIM];
__device__ float g_gk[KBATCH][GDIM];
__device__ float g_h0[HDIM];
__device__ float g_c0[HDIM];

// ---------------- helpers ----------------
__device__ __forceinline__ float sigmoidf_(float x) { return 1.0f / (1.0f + __expf(-x)); }

// swizzled byte offset within a 128x64 fp16 tile (128B rows, 16B groups)
__device__ __forceinline__ uint32_t aoff(int row, int kk) {
    return (uint32_t)(row * 128 + ((((kk >> 3) ^ row) & 7) << 4) + (kk & 7) * 2);
}

__device__ __forceinline__ uint32_t smem_u32(const void* p) {
    uint32_t a;
    asm("{ .reg .u64 t; cvta.to.shared.u64 t, %1; cvt.u32.u64 %0, t; }" : "=r"(a) : "l"(p));
    return a;
}

__device__ __forceinline__ uint32_t hpack(float v0, float v1) {
    __half2 p = __floats2half2_rn(v0, v1);
    return *(uint32_t*)&p;
}

#define CP_ASYNC16(dst, src) \
    asm volatile("cp.async.cg.shared.global [%0], [%1], 16;" :: "r"(dst), "l"(src))
#define CP_COMMIT() asm volatile("cp.async.commit_group;" ::: "memory")
#define CP_WAIT() asm volatile("cp.async.wait_group 2;" ::: "memory")

#define LDMX4(r0, r1, r2, r3, addr) \
    asm volatile("ldmatrix.sync.aligned.m8n8.x4.shared.b16 {%0,%1,%2,%3}, [%4];" \
        : "=r"(r0), "=r"(r1), "=r"(r2), "=r"(r3) : "r"(addr))
#define MMA16816(d, a, b0, b1) \
    asm volatile("mma.sync.aligned.m16n8k16.row.col.f32.f16.f16.f32 " \
        "{%0,%1,%2,%3},{%4,%5,%6,%7},{%8,%9},{%0,%1,%2,%3};" \
        : "+f"((d)[0]), "+f"((d)[1]), "+f"((d)[2]), "+f"((d)[3]) \
        : "r"((a)[0]), "r"((a)[1]), "r"((a)[2]), "r"((a)[3]), "r"(b0), "r"(b1))

// ---------------------------------------------------------------------------
// prep: fp16 hi/lo split of weights into swizzled [n][k] tiles.
// B tile col layout (128): warp w (n>>5), gate ((n>>3)&3), out_local (n&7)
// -> W column = gate*1024 + nb*32 + w*8 + ol
// ---------------------------------------------------------------------------
__global__ void prep_W(const float* __restrict__ Wih, const float* __restrict__ Whh)
{
    int kc = blockIdx.x, nb = blockIdx.y;
    int n = threadIdx.x & 127, kh = threadIdx.x >> 7;
    int w = n >> 5, gate = (n >> 3) & 3, ol = n & 7;
    int col = gate * HDIM + nb * 32 + w * 8 + ol;
    char* th = (char*)&g_Wh[nb][kc][0];
    char* tl = (char*)&g_Wl[nb][kc][0];
#pragma unroll
    for (int kk = kh * 32; kk < kh * 32 + 32; kk += 2) {
        float v0, v1;
        if (kc < 16) {
            size_t kg = (size_t)(kc * 64 + kk);
            v0 = Whh[kg * GDIM + col];
            v1 = Whh[(kg + 1) * GDIM + col];
        } else {
            v0 = (kk < DD) ? Wih[(size_t)kk * GDIM + col] : 0.f;
            v1 = (kk + 1 < DD) ? Wih[(size_t)(kk + 1) * GDIM + col] : 0.f;
        }
        float h0 = __half2float(__float2half_rn(v0));
        float h1 = __half2float(__float2half_rn(v1));
        uint32_t off = aoff(n, kk);
        *(uint32_t*)(th + off) = hpack(h0, h1);
        *(uint32_t*)(tl + off) = hpack(v0 - h0, v1 - h1);
    }
}

__global__ void prep_x(const float* __restrict__ x)
{
    int mb = blockIdx.x, t = blockIdx.y;
    int r = threadIdx.x;
    int m = mb * 128 + r;
    char* th = (char*)&g_xh[t][mb][0];
#pragma unroll
    for (int kk = 0; kk < KC; kk += 2) {
        float v0 = (kk < DD) ? x[((size_t)m * TT + t) * DD + kk] : 0.f;
        float v1 = (kk + 1 < DD) ? x[((size_t)m * TT + t) * DD + kk + 1] : 0.f;
        uint32_t off = aoff(r, kk);
        *(uint32_t*)(th + off) = hpack(v0, v1);
    }
}

// ---------------------------------------------------------------------------
// Data step: fp16 mma.sync GEMM, 2 terms (AhBh + AhBl) + fused LSTM cell
// Stage layout: [Ah 16K][Bh 16K][Bl 16K]
// ---------------------------------------------------------------------------
__device__ __forceinline__ void load_chunk(uint32_t smb, int tid, int c,
                                           int t, int pp, int mb, int nb)
{
    if (c < CPT) {
        const char* ah = (c == 16) ? (const char*)&g_xh[t][mb][0]
                                   : (const char*)&g_Ah[pp][mb][c][0];
        const char* bh = (const char*)&g_Wh[nb][c][0];
        const char* bl = (const char*)&g_Wl[nb][c][0];
        uint32_t dst = smb + (c % NSTAGE) * STAGE_BYTES;
        int o = tid * 16;
#pragma unroll
        for (int i = 0; i < 4; i++) {
            CP_ASYNC16(dst + o,                 ah + o);
            CP_ASYNC16(dst + TILE_BYTES + o,    bh + o);
            CP_ASYNC16(dst + 2*TILE_BYTES + o,  bl + o);
            o += 4096;
        }
    }
    CP_COMMIT();
}

__global__ void __launch_bounds__(256, 1)
data_step(const float* __restrict__ bias, int t, int pp)
{
    extern __shared__ __align__(128) char sm[];
    const uint32_t smb = smem_u32(sm);
    const int tid = threadIdx.x, wid = tid >> 5, lane = tid & 31;
    const int nb = blockIdx.x, mb = blockIdx.y;
    const int mw = (wid >> 2) * 64;       // warp m offset
    const int nw = (wid & 3) * 32;        // warp n(col) offset

    float acc[4][4][4];
#pragma unroll
    for (int i = 0; i < 4; i++)
#pragma unroll
        for (int j = 0; j < 4; j++)
#pragma unroll
            for (int q = 0; q < 4; q++) acc[i][j][q] = 0.f;

    load_chunk(smb, tid, 0, t, pp, mb, nb);
    load_chunk(smb, tid, 1, t, pp, mb, nb);
    load_chunk(smb, tid, 2, t, pp, mb, nb);

    // lane geometry
    const int a_row0 = mw + ((lane >> 3) & 1) * 8 + (lane & 7);   // + mi*16
    const int a_ghalf = lane >> 4;
    // B ldmatrix.x4: m0=(ni,kh0) m1=(ni,kh1) m2=(ni+1,kh0) m3=(ni+1,kh1)
    const int b_row0 = nw + ((lane >> 4) & 1) * 8 + (lane & 7);   // + 16 for ni 2,3
    const int b_ghalf = (lane >> 3) & 1;

    for (int c = 0; c < CPT; c++) {
        CP_WAIT();
        __syncthreads();
        load_chunk(smb, tid, c + NSTAGE - 1, t, pp, mb, nb);

        uint32_t sAh = smb + (c % NSTAGE) * STAGE_BYTES;
        uint32_t sBh = sAh + TILE_BYTES;
        uint32_t sBl = sAh + 2 * TILE_BYTES;
#pragma unroll
        for (int kb = 0; kb < 4; kb++) {
            const uint32_t acsw = (uint32_t)((((2 * kb + a_ghalf) ^ a_row0) & 7) << 4);
            const uint32_t bcsw = (uint32_t)((((2 * kb + b_ghalf) ^ b_row0) & 7) << 4);
            const uint32_t brow = (uint32_t)b_row0 * 128 + bcsw;

            uint32_t ah[4][4], bh[8], bl[8];
#pragma unroll
            for (int mi = 0; mi < 4; mi++) {
                uint32_t ad = sAh + (uint32_t)(a_row0 + mi * 16) * 128 + acsw;
                LDMX4(ah[mi][0], ah[mi][1], ah[mi][2], ah[mi][3], ad);
            }
            LDMX4(bh[0], bh[1], bh[2], bh[3], sBh + brow);
            LDMX4(bh[4], bh[5], bh[6], bh[7], sBh + brow + 2048);
            LDMX4(bl[0], bl[1], bl[2], bl[3], sBl + brow);
            LDMX4(bl[4], bl[5], bl[6], bl[7], sBl + brow + 2048);
#pragma unroll
            for (int ni = 0; ni < 4; ni++)
#pragma unroll
                for (int mi = 0; mi < 4; mi++) {
                    MMA16816(acc[mi][ni], ah[mi], bh[ni * 2], bh[ni * 2 + 1]);
                    MMA16816(acc[mi][ni], ah[mi], bl[ni * 2], bl[ni * 2 + 1]);
                }
        }
    }

    // ---- fused LSTM cell epilogue ----
    const int r4 = lane >> 2;
    const int o0 = nb * 32 + (wid & 3) * 8 + (lane & 3) * 2;
    const int chunk = nb >> 1;
    const int kk0 = o0 & 63;
    float bi0 = bias[o0],            bi1 = bias[o0 + 1];
    float bf0 = bias[HDIM + o0],     bf1 = bias[HDIM + o0 + 1];
    float bg0 = bias[2*HDIM + o0],   bg1 = bias[2*HDIM + o0 + 1];
    float bo0 = bias[3*HDIM + o0],   bo1 = bias[3*HDIM + o0 + 1];
    char* th = (char*)&g_Ah[pp ^ 1][mb][chunk][0];

#pragma unroll
    for (int mi = 0; mi < 4; mi++) {
#pragma unroll
        for (int b2 = 0; b2 < 2; b2++) {
            int mrow = mw + mi * 16 + r4 + b2 * 8;
            int m = mb * 128 + mrow;
            size_t cidx = (size_t)m * HDIM + o0;
            float2 cold = *(float2*)&g_c[cidx];
            float gi0 = acc[mi][0][b2 * 2],     gi1 = acc[mi][0][b2 * 2 + 1];
            float gf0 = acc[mi][1][b2 * 2],     gf1 = acc[mi][1][b2 * 2 + 1];
            float gg0 = acc[mi][2][b2 * 2],     gg1 = acc[mi][2][b2 * 2 + 1];
            float go0 = acc[mi][3][b2 * 2],     go1 = acc[mi][3][b2 * 2 + 1];
            float cn0 = sigmoidf_(gf0 + bf0) * cold.x
                      + sigmoidf_(gi0 + bi0) * tanhf(gg0 + bg0);
            float cn1 = sigmoidf_(gf1 + bf1) * cold.y
                      + sigmoidf_(gi1 + bi1) * tanhf(gg1 + bg1);
            float h0 = sigmoidf_(go0 + bo0) * tanhf(cn0);
            float h1 = sigmoidf_(go1 + bo1) * tanhf(cn1);
            *(float2*)&g_c[cidx] = make_float2(cn0, cn1);
            *(float2*)&g_hf[cidx] = make_float2(h0, h1);
            *(uint32_t*)(th + aoff(mrow, kk0)) = hpack(h0, h1);
        }
    }
}

// ---------------------------------------------------------------------------
// Key pass (batch 8): split-K SIMT GEMM, one thread per column (all 8 rows)
// ---------------------------------------------------------------------------
#define KSPLIT 32
#define KSLICE 33
__global__ void key_gemm(const float* __restrict__ key,
                         const float* __restrict__ Wih,
                         const float* __restrict__ Whh,
                         int t, int p)
{
    __shared__ float hs[KBATCH][KSLICE];
    const int cb = blockIdx.x;   // 16 col-blocks of 256
    const int ks = blockIdx.y;   // 32 K-splits
    const int tid = threadIdx.x;
    const int k0 = ks * KSLICE;
    const int k1 = min(k0 + KSLICE, HDIM + DD);

    for (int i = tid; i < KBATCH * KSLICE; i += 256) {
        int mm = i / KSLICE, kk = k0 + i % KSLICE;
        float v = 0.f;
        if (kk < HDIM) v = g_hk[p][mm * HDIM + kk];
        else if (kk < HDIM + DD) v = key[(size_t)(mm * TT + t) * DD + (kk - HDIM)];
        hs[mm][i % KSLICE] = v;
    }
    __syncthreads();

    const int col = cb * 256 + tid;
    float acc[KBATCH];
#pragma unroll
    for (int mm = 0; mm < KBATCH; mm++) acc[mm] = 0.f;

    const int k1h = min(k1, HDIM);
    for (int kk = k0; kk < k1h; kk++) {
        float w = Whh[(size_t)kk * GDIM + col];
        int j = kk - k0;
#pragma unroll
        for (int mm = 0; mm < KBATCH; mm++) acc[mm] += hs[mm][j] * w;
    }
    for (int kk = max(k0, HDIM); kk < k1; kk++) {
        float w = Wih[(size_t)(kk - HDIM) * GDIM + col];
        int j = kk - k0;
#pragma unroll
        for (int mm = 0; mm < KBATCH; mm++) acc[mm] += hs[mm][j] * w;
    }
#pragma unroll
    for (int mm = 0; mm < KBATCH; mm++)
        atomicAdd(&g_gk[mm][col], acc[mm]);
}

__global__ void key_cell(const float* __restrict__ bias, int p)
{
    int i = blockIdx.x * blockDim.x + threadIdx.x;
    if (i >= KBATCH * HDIM) return;
    int mm = i >> 10, n = i & (HDIM - 1);
    float gi = g_gk[mm][n] + bias[n];
    float gf = g_gk[mm][HDIM + n] + bias[HDIM + n];
    float gg = g_gk[mm][2 * HDIM + n] + bias[2 * HDIM + n];
    float go = g_gk[mm][3 * HDIM + n] + bias[3 * HDIM + n];
    g_gk[mm][n] = 0.f; g_gk[mm][HDIM + n] = 0.f;
    g_gk[mm][2 * HDIM + n] = 0.f; g_gk[mm][3 * HDIM + n] = 0.f;
    float cold = g_ck[mm * HDIM + n];
    float cn = sigmoidf_(gf) * cold + sigmoidf_(gi) * tanhf(gg);
    g_ck[mm * HDIM + n] = cn;
    g_hk[1 - p][mm * HDIM + n] = sigmoidf_(go) * tanhf(cn);
}

__global__ void key_init()
{
    int i = blockIdx.x * blockDim.x + threadIdx.x;
    if (i < KBATCH * HDIM) { g_hk[0][i] = 0.f; g_ck[i] = 0.f; }
    if (i < KBATCH * GDIM) g_gk[i / GDIM][i % GDIM] = 0.f;
}

__global__ void key_mean(int p)
{
    int n = blockIdx.x * blockDim.x + threadIdx.x;
    if (n < HDIM) {
        float sh = 0.f, sc = 0.f;
        for (int m = 0; m < KBATCH; m++) {
            sh += g_hk[p][m * HDIM + n];
            sc += g_ck[m * HDIM + n];
        }
        g_h0[n] = sh * (1.0f / KBATCH);
        g_c0[n] = sc * (1.0f / KBATCH);
    }
}

// broadcast h0/c0 into A tiles + c
__global__ void bcast_init()
{
    int mb = blockIdx.x, ch = blockIdx.y;
    int r = threadIdx.x;
    int m = mb * 128 + r;
    char* th = (char*)&g_Ah[0][mb][ch][0];
#pragma unroll
    for (int kk = 0; kk < KC; kk += 2) {
        int n = ch * KC + kk;
        float v0 = g_h0[n], v1 = g_h0[n + 1];
        *(uint32_t*)(th + aoff(r, kk)) = hpack(v0, v1);
        *(float2*)&g_c[(size_t)m * HDIM + n] = make_float2(g_c0[n], g_c0[n + 1]);
    }
}

// ---------------------------------------------------------------------------
__global__ void classify(const float* __restrict__ Wcls,
                         const float* __restrict__ bcls,
                         float* __restrict__ out)
{
    int gw = (blockIdx.x * blockDim.x + threadIdx.x) >> 5;
    int lane = threadIdx.x & 31;
    if (gw >= BB) return;
    const float* hr = &g_hf[(size_t)gw * HDIM];
    float acc[10];
#pragma unroll
    for (int c = 0; c < 10; c++) acc[c] = 0.f;
    for (int k = lane; k < HDIM; k += 32) {
        float hv = hr[k];
#pragma unroll
        for (int c = 0; c < 10; c++) acc[c] += hv * Wcls[k * 10 + c];
    }
#pragma unroll
    for (int c = 0; c < 10; c++) {
#pragma unroll
        for (int off = 16; off > 0; off >>= 1)
            acc[c] += __shfl_down_sync(0xffffffffu, acc[c], off);
    }
    if (lane == 0) {
#pragma unroll
        for (int c = 0; c < 10; c++)
            out[(size_t)gw * 10 + c] = acc[c] + bcls[c];
    }
}

// ---------------------------------------------------------------------------
extern "C" void kernel_launch(void* const* d_in, const int* in_sizes, int n_in,
                              void* d_out, int out_size)
{
    const float* x    = (const float*)d_in[0];
    const float* key  = (const float*)d_in[1];
    const float* Wih  = (const float*)d_in[2];
    const float* Whh  = (const float*)d_in[3];
    const float* b    = (const float*)d_in[4];
    const float* Wcls = (const float*)d_in[5];
    const float* bcls = (const float*)d_in[6];
    float* out = (float*)d_out;

    cudaFuncSetAttribute(data_step, cudaFuncAttributeMaxDynamicSharedMemorySize,
                         SMEM_DATA);

    prep_W<<<dim3(CPT, NBK), 256>>>(Wih, Whh);
    prep_x<<<dim3(MBK, TT), 128>>>(x);

    key_init<<<(KBATCH * GDIM + 255) / 256, 256>>>();
    for (int t = 0; t < TT; t++) {
        key_gemm<<<dim3(GDIM / 256, KSPLIT), 256>>>(key, Wih, Whh, t, t & 1);
        key_cell<<<(KBATCH * HDIM + 255) / 256, 256>>>(b, t & 1);
    }
    key_mean<<<(HDIM + 255) / 256, 256>>>(0);
    bcast_init<<<dim3(MBK, 16), 128>>>();

    dim3 grid(NBK, MBK);
    for (int t = 0; t < TT; t++)
        data_step<<<grid, 256, SMEM_DATA>>>(b, t, t & 1);

    classify<<<BB / 8, 256>>>(Wcls, bcls, out);
}